// round 9
// baseline (speedup 1.0000x reference)
#include <cuda_runtime.h>
#include <cuda_bf16.h>
#include <cstdint>

#define GK   192
#define NPIX 65536

// ---------------------------------------------------------------------------
// scratch (allocation-free rule: __device__ globals)
// ---------------------------------------------------------------------------
__device__ float g_qkv[75497472];                         // [2][576][65536] f32
__device__ __align__(16) unsigned short g_bth[25165824];  // [2][65536][192] bf16 hi
__device__ __align__(16) unsigned short g_btl[25165824];  // [2][65536][192] bf16 lo
__device__ __align__(16) unsigned short g_wqh[110592], g_wql[110592];
__device__ __align__(16) unsigned short g_wph[36864],  g_wpl[36864];

// ---------------------------------------------------------------------------
__device__ __forceinline__ uint32_t smem_u32(const void* p) {
    uint32_t a;
    asm("{ .reg .u64 t; cvta.to.shared.u64 t, %1; cvt.u32.u64 %0, t; }"
        : "=r"(a) : "l"(p));
    return a;
}

__device__ __forceinline__ void cp_async16(uint32_t dst, const void* src) {
    asm volatile("cp.async.cg.shared.global [%0], [%1], 16;"
                 :: "r"(dst), "l"(src) : "memory");
}

#define LDSM_X4(r0, r1, r2, r3, a) \
    asm volatile("ldmatrix.sync.aligned.m8n8.x4.shared.b16 {%0,%1,%2,%3}, [%4];" \
                 : "=r"(r0), "=r"(r1), "=r"(r2), "=r"(r3) : "r"(a))

#define MMA16816(d, a, b) \
    asm volatile("mma.sync.aligned.m16n8k16.row.col.f32.bf16.bf16.f32 " \
                 "{%0,%1,%2,%3}, {%4,%5,%6,%7}, {%8,%9}, {%0,%1,%2,%3};" \
                 : "+f"((d)[0]), "+f"((d)[1]), "+f"((d)[2]), "+f"((d)[3]) \
                 : "r"((a)[0]), "r"((a)[1]), "r"((a)[2]), "r"((a)[3]), \
                   "r"((b)[0]), "r"((b)[1]))

// ---------------------------------------------------------------------------
// convert + transpose: src f32 [2][192][65536] -> dhi/dlo bf16 [2][65536][192]
// ---------------------------------------------------------------------------
__global__ __launch_bounds__(256) void convtrans(
    const float* __restrict__ src,
    unsigned short* __restrict__ dhi,
    unsigned short* __restrict__ dlo)
{
    __shared__ float sm[32][33];
    const int p0 = blockIdx.x * 32, c0 = blockIdx.y * 32, b = blockIdx.z;
    const float* s = src + (size_t)b * GK * NPIX;
    const int tc = threadIdx.x & 31, tr = threadIdx.x >> 5;

    #pragma unroll
    for (int i = 0; i < 4; i++) {
        int cl = tr + i * 8;
        sm[cl][tc] = s[(size_t)(c0 + cl) * NPIX + p0 + tc];
    }
    __syncthreads();

    const size_t obase = (size_t)b * NPIX * GK;
    #pragma unroll
    for (int i = 0; i < 4; i++) {
        int pl = tr + i * 8;
        float v = sm[tc][pl];
        __nv_bfloat16 h = __float2bfloat16(v);
        __nv_bfloat16 l = __float2bfloat16(v - __bfloat162float(h));
        size_t o = obase + (size_t)(p0 + pl) * GK + c0 + tc;
        dhi[o] = *(unsigned short*)&h;
        dlo[o] = *(unsigned short*)&l;
    }
}

__global__ void wconvert(const float* __restrict__ w, int n,
                         unsigned short* __restrict__ hi,
                         unsigned short* __restrict__ lo)
{
    int i = blockIdx.x * 256 + threadIdx.x;
    if (i < n) {
        float v = w[i];
        __nv_bfloat16 h = __float2bfloat16(v);
        __nv_bfloat16 l = __float2bfloat16(v - __bfloat162float(h));
        hi[i] = *(unsigned short*)&h;
        lo[i] = *(unsigned short*)&l;
    }
}

// ---------------------------------------------------------------------------
// mma.sync GEMM:  C[b,m,n] = sum_k A[m,k] * B[b,n,k]   (3-term bf16 split)
// CTA 64(M) x 128(N), 8 warps (2Mx4N), warp 32x32 via 2x4 m16n8k16 tiles.
// K=192 in SIX 32-chunks (pitch 40: conflict-free), double-buffered:
// 61.4 KB smem -> 3 CTAs/SM (was 2) to cover ldmatrix latency + barrier skew.
// ---------------------------------------------------------------------------
__global__ __launch_bounds__(256) void gemm_mma(
    const unsigned short* __restrict__ Ahi,
    const unsigned short* __restrict__ Alo,
    const unsigned short* __restrict__ Bhi,
    const unsigned short* __restrict__ Blo,
    float* __restrict__ Cm, int Mtot)
{
    extern __shared__ __align__(16) unsigned short smem[];
    const int t = threadIdx.x, lane = t & 31, w = t >> 5;
    const int bM = blockIdx.x * 64;
    const size_t bN = (size_t)blockIdx.y * 128;
    const int batch = blockIdx.z;
    const int wm0 = (w >> 2) * 32;
    const int wn0 = (w & 3) * 32;

    const uint32_t sb = smem_u32(smem);
    // per buffer (15360 elems = 30720 B):
    //   A [hl][64][40] at elem 0 (hl stride 2560)
    //   B [hl][128][40] at elem 5120 (hl stride 5120)

    const unsigned short* gA[2] = { Ahi + (size_t)bM * GK, Alo + (size_t)bM * GK };
    const size_t boff = ((size_t)batch * NPIX + bN) * GK;
    const unsigned short* gB[2] = { Bhi + boff, Blo + boff };

    auto issue_chunk = [&](int c) {
        const uint32_t sbase = sb + (uint32_t)(c & 1) * 30720u;
        #pragma unroll
        for (int i = 0; i < 2; i++) {              // A: 512 16B-chunks
            int id = t + i * 256;
            int hl = id >> 8, rem = id & 255;
            int row = rem >> 2, c8 = rem & 3;
            uint32_t d = sbase + (uint32_t)(hl * 2560 + row * 40 + c8 * 8) * 2u;
            cp_async16(d, gA[hl] + row * GK + c * 32 + c8 * 8);
        }
        #pragma unroll
        for (int i = 0; i < 4; i++) {              // B: 1024 16B-chunks
            int id = t + i * 256;
            int hl = id >> 9, rem = id & 511;
            int row = rem >> 2, c8 = rem & 3;
            uint32_t d = sbase + (uint32_t)(5120 + hl * 5120 + row * 40 + c8 * 8) * 2u;
            cp_async16(d, gB[hl] + row * GK + c * 32 + c8 * 8);
        }
        asm volatile("cp.async.commit_group;" ::: "memory");
    };

    float acc[2][4][4];
    #pragma unroll
    for (int mi = 0; mi < 2; mi++)
        #pragma unroll
        for (int ni = 0; ni < 4; ni++)
            #pragma unroll
            for (int r = 0; r < 4; r++) acc[mi][ni][r] = 0.f;

    const int arow  = lane & 15;
    const int akoff = (lane >> 4) * 8;
    const int bg    = lane >> 3;
    const int brow8 = lane & 7;

    issue_chunk(0);
    #pragma unroll 1
    for (int c = 0; c < 6; c++) {
        if (c + 1 < 6) {
            issue_chunk(c + 1);
            asm volatile("cp.async.wait_group 1;" ::: "memory");
        } else {
            asm volatile("cp.async.wait_group 0;" ::: "memory");
        }
        __syncthreads();

        const uint32_t sbase = sb + (uint32_t)(c & 1) * 30720u;
        #pragma unroll
        for (int ks = 0; ks < 2; ks++) {
            const int k0 = ks * 16;
            uint32_t ah[2][4], al[2][4], bh[4][2], bl[4][2];
            #pragma unroll
            for (int mi = 0; mi < 2; mi++) {
                uint32_t off = (uint32_t)((wm0 + mi * 16 + arow) * 40 + k0 + akoff) * 2u;
                LDSM_X4(ah[mi][0], ah[mi][1], ah[mi][2], ah[mi][3], sbase + off);
                LDSM_X4(al[mi][0], al[mi][1], al[mi][2], al[mi][3],
                        sbase + 2560u * 2u + off);
            }
            #pragma unroll
            for (int np = 0; np < 2; np++) {
                uint32_t off = (uint32_t)(5120
                    + (wn0 + (2 * np + (bg >> 1)) * 8 + brow8) * 40
                    + k0 + (bg & 1) * 8) * 2u;
                LDSM_X4(bh[2*np][0], bh[2*np][1], bh[2*np+1][0], bh[2*np+1][1],
                        sbase + off);
                LDSM_X4(bl[2*np][0], bl[2*np][1], bl[2*np+1][0], bl[2*np+1][1],
                        sbase + 5120u * 2u + off);
            }
            #pragma unroll
            for (int mi = 0; mi < 2; mi++)
                #pragma unroll
                for (int ni = 0; ni < 4; ni++)
                    MMA16816(acc[mi][ni], ah[mi], bh[ni]);
            #pragma unroll
            for (int mi = 0; mi < 2; mi++)
                #pragma unroll
                for (int ni = 0; ni < 4; ni++)
                    MMA16816(acc[mi][ni], ah[mi], bl[ni]);
            #pragma unroll
            for (int mi = 0; mi < 2; mi++)
                #pragma unroll
                for (int ni = 0; ni < 4; ni++)
                    MMA16816(acc[mi][ni], al[mi], bh[ni]);
        }
        __syncthreads();
    }

    float* C = Cm + (size_t)batch * (size_t)Mtot * NPIX;
    const int mr = lane >> 2, nc = (lane & 3) * 2;
    #pragma unroll
    for (int mi = 0; mi < 2; mi++)
        #pragma unroll
        for (int ni = 0; ni < 4; ni++) {
            const size_t m = (size_t)(bM + wm0 + mi * 16 + mr);
            const size_t n = bN + wn0 + ni * 8 + nc;
            float* a = acc[mi][ni];
            *(float2*)&C[m * NPIX + n]       = make_float2(a[0], a[1]);
            *(float2*)&C[(m + 8) * NPIX + n] = make_float2(a[2], a[3]);
        }
}

// ---------------------------------------------------------------------------
// Fused depthwise-3x3 + 8x8-window channel attention, fused bf16 epilogue.
// Matmuls use 64-thread 6x6 (logits) and 6x8 (PV) register tiles to cut
// smem traffic ~2x (kernel is LDS-bandwidth-bound).
// ---------------------------------------------------------------------------
__global__ __launch_bounds__(256, 3) void window_attn(
    const float* __restrict__ dww,    // [576*9]
    const float* __restrict__ tempr)  // [4]
{
    const int t    = threadIdx.x;
    const int head = blockIdx.x & 3;
    const int win  = blockIdx.x >> 2;
    const int b    = win >> 10;
    const int hn   = (win >> 5) & 31;
    const int wn   = win & 31;
    const int y0   = hn << 3, x0 = wn << 3;

    __shared__ float sq[48 * 64];
    __shared__ float skT[64 * 52];       // later reused as u32 staging [64][52]
    __shared__ float sv[48 * 64];
    __shared__ float scratch[2400];      // halo [24][100] -> attn [48][49]
    __shared__ float qin[48], kin[48];

    const size_t qkv_base = (size_t)b * 576 * NPIX;

    float hreg[10];
    auto load_halo = [&](int gch0) {
        #pragma unroll
        for (int i = 0; i < 10; i++) {
            int e = t + i * 256;
            float v = 0.f;
            if (e < 2400) {
                int c  = e / 100;
                int px = e - c * 100;
                int iy = px / 10;
                int ix = px - iy * 10;
                int gy = y0 - 1 + iy;
                int gx = x0 - 1 + ix;
                if ((unsigned)gy < 256u && (unsigned)gx < 256u)
                    v = g_qkv[qkv_base + (size_t)(gch0 + c) * NPIX + gy * 256 + gx];
            }
            hreg[i] = v;
        }
    };

    load_halo(head * 48);
    #pragma unroll 1
    for (int p = 0; p < 6; p++) {
        const int tensor = p >> 1;
        const int half   = p & 1;
        const int gch0   = tensor * 192 + head * 48 + half * 24;

        #pragma unroll
        for (int i = 0; i < 10; i++) {
            int e = t + i * 256;
            if (e < 2400) scratch[e] = hreg[i];
        }
        __syncthreads();

        if (p < 5) {
            const int np = p + 1;
            load_halo((np >> 1) * 192 + head * 48 + (np & 1) * 24);
        }

        #pragma unroll
        for (int u = 0; u < 6; u++) {
            int e  = t + u * 256;
            int c  = e >> 6;
            int pp = e & 63;
            int p1 = pp >> 3, p2 = pp & 7;
            const float* wr = dww + (gch0 + c) * 9;
            const float* tp = scratch + c * 100 + p1 * 10 + p2;
            float s = tp[ 0]*wr[0] + tp[ 1]*wr[1] + tp[ 2]*wr[2]
                    + tp[10]*wr[3] + tp[11]*wr[4] + tp[12]*wr[5]
                    + tp[20]*wr[6] + tp[21]*wr[7] + tp[22]*wr[8];
            int ch = half * 24 + c;
            if      (tensor == 0) sq[ch * 64 + pp]  = s;
            else if (tensor == 1) skT[pp * 52 + ch] = s;
            else                  sv[ch * 64 + pp]  = s;
        }
        __syncthreads();
    }

    if (t < 48) {
        float s = 0.f;
        #pragma unroll 8
        for (int d = 0; d < 64; d++) {
            float x = sq[t * 64 + ((d + t) & 63)];
            s = fmaf(x, x, s);
        }
        qin[t] = 1.f / fmaxf(sqrtf(s), 1e-12f);
    } else if (t >= 128 && t < 176) {
        int j = t - 128;
        float s = 0.f;
        #pragma unroll 8
        for (int d = 0; d < 64; d++) {
            float x = skT[d * 52 + j];
            s = fmaf(x, x, s);
        }
        kin[j] = 1.f / fmaxf(sqrtf(s), 1e-12f);
    }
    __syncthreads();

    float* sattn = scratch;
    const float tscale = __ldg(&tempr[head]);

    // ---- logits: 6x6 register tile on 64 threads ----
    if (t < 64) {
        const int ti = t >> 3;            // 0..7 -> i0 = 6*ti
        const int tj = t & 7;             // 0..7 -> j0 = 6*tj
        const int i0 = ti * 6, j0 = tj * 6;
        float acc[6][6];
        #pragma unroll
        for (int r = 0; r < 6; r++)
            #pragma unroll
            for (int s = 0; s < 6; s++) acc[r][s] = 0.f;

        for (int d0 = 0; d0 < 64; d0 += 4) {
            float4 qv[6];
            #pragma unroll
            for (int r = 0; r < 6; r++)
                qv[r] = *(const float4*)&sq[(i0 + r) * 64 + d0];
            #pragma unroll
            for (int dd = 0; dd < 4; dd++) {
                float kv[6];
                #pragma unroll
                for (int s = 0; s < 6; s++) kv[s] = skT[(d0 + dd) * 52 + j0 + s];
                #pragma unroll
                for (int r = 0; r < 6; r++) {
                    float qd = (dd == 0) ? qv[r].x : (dd == 1) ? qv[r].y
                             : (dd == 2) ? qv[r].z : qv[r].w;
                    #pragma unroll
                    for (int s = 0; s < 6; s++)
                        acc[r][s] = fmaf(qd, kv[s], acc[r][s]);
                }
            }
        }
        #pragma unroll
        for (int r = 0; r < 6; r++) {
            float qi = qin[i0 + r] * tscale;
            #pragma unroll
            for (int s = 0; s < 6; s++)
                sattn[(i0 + r) * 49 + j0 + s] = acc[r][s] * qi * kin[j0 + s];
        }
    }
    __syncthreads();

    if (t < 48) {
        float m = -1e30f;
        #pragma unroll 8
        for (int j = 0; j < 48; j++) m = fmaxf(m, sattn[t * 49 + j]);
        float s = 0.f;
        #pragma unroll 8
        for (int j = 0; j < 48; j++) {
            float e = __expf(sattn[t * 49 + j] - m);
            sattn[t * 49 + j] = e;
            s += e;
        }
        float inv = 1.f / s;
        #pragma unroll 8
        for (int j = 0; j < 48; j++) sattn[t * 49 + j] *= inv;
    }
    __syncthreads();

    // ---- out = attn @ v ; 6x8 register tile on 64 threads ----
    uint32_t* stg = (uint32_t*)skT;                // [64 pix][52 ch]
    float pacc[6][8];
    const int td = t & 7, tip = t >> 3;
    const int d0 = td * 8, i0p = tip * 6;
    if (t < 64) {
        #pragma unroll
        for (int r = 0; r < 6; r++)
            #pragma unroll
            for (int s = 0; s < 8; s++) pacc[r][s] = 0.f;

        for (int j = 0; j < 48; j++) {
            float4 v0 = *(const float4*)&sv[j * 64 + d0];
            float4 v1 = *(const float4*)&sv[j * 64 + d0 + 4];
            #pragma unroll
            for (int r = 0; r < 6; r++) {
                float a = sattn[(i0p + r) * 49 + j];
                pacc[r][0] = fmaf(a, v0.x, pacc[r][0]);
                pacc[r][1] = fmaf(a, v0.y, pacc[r][1]);
                pacc[r][2] = fmaf(a, v0.z, pacc[r][2]);
                pacc[r][3] = fmaf(a, v0.w, pacc[r][3]);
                pacc[r][4] = fmaf(a, v1.x, pacc[r][4]);
                pacc[r][5] = fmaf(a, v1.y, pacc[r][5]);
                pacc[r][6] = fmaf(a, v1.z, pacc[r][6]);
                pacc[r][7] = fmaf(a, v1.w, pacc[r][7]);
            }
        }
    }
    __syncthreads();                               // skT readers all done
    if (t < 64) {
        #pragma unroll
        for (int r = 0; r < 6; r++)
            #pragma unroll
            for (int s = 0; s < 8; s++) {
                float v = pacc[r][s];
                __nv_bfloat16 h = __float2bfloat16(v);
                __nv_bfloat16 l = __float2bfloat16(v - __bfloat162float(h));
                stg[(d0 + s) * 52 + i0p + r] =
                    (uint32_t)*(unsigned short*)&h
                    | ((uint32_t)*(unsigned short*)&l << 16);
            }
    }
    __syncthreads();

    // cooperative transposed writeout: [pix][ch] -> g_bth/g_btl [b][pix][192]
    #pragma unroll
    for (int i = 0; i < 6; i++) {
        int id = t + i * 256;
        int row = id / 24, cp = id - row * 24;
        int c = cp * 2;
        uint32_t w0 = stg[row * 52 + c];
        uint32_t w1 = stg[row * 52 + c + 1];
        int p1 = row >> 3, p2 = row & 7;
        size_t o = ((size_t)b * NPIX + (size_t)(y0 + p1) * 256 + (x0 + p2)) * GK
                 + head * 48 + c;
        *(ushort2*)&g_bth[o] = make_ushort2((unsigned short)w0, (unsigned short)w1);
        *(ushort2*)&g_btl[o] = make_ushort2((unsigned short)(w0 >> 16),
                                            (unsigned short)(w1 >> 16));
    }
}

// ---------------------------------------------------------------------------
extern "C" void kernel_launch(void* const* d_in, const int* in_sizes, int n_in,
                              void* d_out, int out_size)
{
    const float *x = nullptr, *qw = nullptr, *dw = nullptr, *pw = nullptr, *tp = nullptr;
    for (int i = 0; i < n_in; i++) {
        switch (in_sizes[i]) {
            case 25165824: x  = (const float*)d_in[i]; break;  // x [2,192,256,256]
            case 110592:   qw = (const float*)d_in[i]; break;  // qkv_w [576,192]
            case 5184:     dw = (const float*)d_in[i]; break;  // dw_w [576,1,3,3]
            case 36864:    pw = (const float*)d_in[i]; break;  // proj_w [192,192]
            case 4:        tp = (const float*)d_in[i]; break;  // temperature [4]
        }
    }

    void *qkvp, *bthp, *btlp, *wqhp, *wqlp, *wphp, *wplp;
    cudaGetSymbolAddress(&qkvp, g_qkv);
    cudaGetSymbolAddress(&bthp, g_bth);
    cudaGetSymbolAddress(&btlp, g_btl);
    cudaGetSymbolAddress(&wqhp, g_wqh);
    cudaGetSymbolAddress(&wqlp, g_wql);
    cudaGetSymbolAddress(&wphp, g_wph);
    cudaGetSymbolAddress(&wplp, g_wpl);

    const int GEMM_SMEM = 2 * 30720;             // 61440 B -> 3 CTAs/SM
    cudaFuncSetAttribute(gemm_mma, cudaFuncAttributeMaxDynamicSharedMemorySize, GEMM_SMEM);

    wconvert<<<(110592 + 255) / 256, 256>>>(qw, 110592,
        (unsigned short*)wqhp, (unsigned short*)wqlp);
    wconvert<<<(36864 + 255) / 256, 256>>>(pw, 36864,
        (unsigned short*)wphp, (unsigned short*)wplp);

    // 1) x -> x^T bf16 hi/lo
    convtrans<<<dim3(2048, 6, 2), 256>>>(x,
        (unsigned short*)bthp, (unsigned short*)btlp);

    // 2) qkv GEMM (mma.sync): [576,192] x [65536,192]^T
    gemm_mma<<<dim3(9, 512, 2), 256, GEMM_SMEM>>>(
        (const unsigned short*)wqhp, (const unsigned short*)wqlp,
        (const unsigned short*)bthp, (const unsigned short*)btlp,
        (float*)qkvp, 576);

    // 3) fused depthwise 3x3 + attention; writes bf16 hi/lo transposed
    window_attn<<<8192, 256>>>(dw, tp);

    // 4) proj GEMM -> d_out
    gemm_mma<<<dim3(3, 512, 2), 256, GEMM_SMEM>>>(
        (const unsigned short*)wphp, (const unsigned short*)wplp,
        (const unsigned short*)bthp, (const unsigned short*)btlp,
        (float*)d_out, 192);
}

// round 10
// speedup vs baseline: 1.0867x; 1.0867x over previous
#include <cuda_runtime.h>
#include <cuda_bf16.h>
#include <cstdint>

#define GK   192
#define NPIX 65536

// ---------------------------------------------------------------------------
// scratch (allocation-free rule: __device__ globals)
// ---------------------------------------------------------------------------
__device__ float g_qkv[75497472];                         // [2][65536][576] f32 (pixel-major)
__device__ __align__(16) unsigned short g_bth[25165824];  // [2][65536][192] bf16 hi
__device__ __align__(16) unsigned short g_btl[25165824];  // [2][65536][192] bf16 lo
__device__ __align__(16) unsigned short g_wqh[110592], g_wql[110592];
__device__ __align__(16) unsigned short g_wph[36864],  g_wpl[36864];

// ---------------------------------------------------------------------------
__device__ __forceinline__ uint32_t smem_u32(const void* p) {
    uint32_t a;
    asm("{ .reg .u64 t; cvta.to.shared.u64 t, %1; cvt.u32.u64 %0, t; }"
        : "=r"(a) : "l"(p));
    return a;
}

__device__ __forceinline__ void cp_async16(uint32_t dst, const void* src) {
    asm volatile("cp.async.cg.shared.global [%0], [%1], 16;"
                 :: "r"(dst), "l"(src) : "memory");
}

#define LDSM_X4(r0, r1, r2, r3, a) \
    asm volatile("ldmatrix.sync.aligned.m8n8.x4.shared.b16 {%0,%1,%2,%3}, [%4];" \
                 : "=r"(r0), "=r"(r1), "=r"(r2), "=r"(r3) : "r"(a))

#define MMA16816(d, a, b) \
    asm volatile("mma.sync.aligned.m16n8k16.row.col.f32.bf16.bf16.f32 " \
                 "{%0,%1,%2,%3}, {%4,%5,%6,%7}, {%8,%9}, {%0,%1,%2,%3};" \
                 : "+f"((d)[0]), "+f"((d)[1]), "+f"((d)[2]), "+f"((d)[3]) \
                 : "r"((a)[0]), "r"((a)[1]), "r"((a)[2]), "r"((a)[3]), \
                   "r"((b)[0]), "r"((b)[1]))

// ---------------------------------------------------------------------------
// convert + transpose: src f32 [2][192][65536] -> dhi/dlo bf16 [2][65536][192]
// ---------------------------------------------------------------------------
__global__ __launch_bounds__(256) void convtrans(
    const float* __restrict__ src,
    unsigned short* __restrict__ dhi,
    unsigned short* __restrict__ dlo)
{
    __shared__ float sm[32][33];
    const int p0 = blockIdx.x * 32, c0 = blockIdx.y * 32, b = blockIdx.z;
    const float* s = src + (size_t)b * GK * NPIX;
    const int tc = threadIdx.x & 31, tr = threadIdx.x >> 5;

    #pragma unroll
    for (int i = 0; i < 4; i++) {
        int cl = tr + i * 8;
        sm[cl][tc] = s[(size_t)(c0 + cl) * NPIX + p0 + tc];
    }
    __syncthreads();

    const size_t obase = (size_t)b * NPIX * GK;
    #pragma unroll
    for (int i = 0; i < 4; i++) {
        int pl = tr + i * 8;
        float v = sm[tc][pl];
        __nv_bfloat16 h = __float2bfloat16(v);
        __nv_bfloat16 l = __float2bfloat16(v - __bfloat162float(h));
        size_t o = obase + (size_t)(p0 + pl) * GK + c0 + tc;
        dhi[o] = *(unsigned short*)&h;
        dlo[o] = *(unsigned short*)&l;
    }
}

__global__ void wconvert(const float* __restrict__ w, int n,
                         unsigned short* __restrict__ hi,
                         unsigned short* __restrict__ lo)
{
    int i = blockIdx.x * 256 + threadIdx.x;
    if (i < n) {
        float v = w[i];
        __nv_bfloat16 h = __float2bfloat16(v);
        __nv_bfloat16 l = __float2bfloat16(v - __bfloat162float(h));
        hi[i] = *(unsigned short*)&h;
        lo[i] = *(unsigned short*)&l;
    }
}

// ---------------------------------------------------------------------------
// qkv GEMM, pixel-major output:  C[b, pix, och] = sum_k A[b,pix,k] * W[och,k]
// CTA 128(M=pix) x 64(N=och), 8 warps (4Mx2N), warp 32x32 via 2x4 m16n8k16.
// K=192 in six 32-chunks (pitch 40, conflict-free), cp.async double-buffered.
// Grid launched N-fastest so A tiles are L2-resident across the 9 och-tiles.
// ---------------------------------------------------------------------------
__global__ __launch_bounds__(256) void gemm_nt(
    const unsigned short* __restrict__ Ahi,   // [2][NPIX][192] (pixels)
    const unsigned short* __restrict__ Alo,
    const unsigned short* __restrict__ Whi,   // [576][192] weights
    const unsigned short* __restrict__ Wlo,
    float* __restrict__ Cm, int Ntot)
{
    extern __shared__ __align__(16) unsigned short smem[];
    const int t = threadIdx.x, lane = t & 31, w = t >> 5;
    const int bN = blockIdx.x * 64;
    const size_t bM = (size_t)blockIdx.y * 128;
    const int batch = blockIdx.z;
    const int wm0 = (w & 3) * 32;      // 4 M-warps
    const int wn0 = (w >> 2) * 32;     // 2 N-warps

    const uint32_t sb = smem_u32(smem);
    // per buffer (15360 elems = 30720 B):
    //   A [hl][128][40] at elem 0   (hl stride 5120)
    //   W [hl][64][40]  at elem 10240 (hl stride 2560)

    const size_t aoff = ((size_t)batch * NPIX + bM) * GK;
    const unsigned short* gA[2] = { Ahi + aoff, Alo + aoff };
    const unsigned short* gW[2] = { Whi + (size_t)bN * GK, Wlo + (size_t)bN * GK };

    auto issue_chunk = [&](int c) {
        const uint32_t sbase = sb + (uint32_t)(c & 1) * 30720u;
        #pragma unroll
        for (int i = 0; i < 4; i++) {              // A: 1024 16B-chunks
            int id = t + i * 256;
            int hl = id >> 9, rem = id & 511;
            int row = rem >> 2, c8 = rem & 3;
            uint32_t d = sbase + (uint32_t)(hl * 5120 + row * 40 + c8 * 8) * 2u;
            cp_async16(d, gA[hl] + row * GK + c * 32 + c8 * 8);
        }
        #pragma unroll
        for (int i = 0; i < 2; i++) {              // W: 512 16B-chunks
            int id = t + i * 256;
            int hl = id >> 8, rem = id & 255;
            int row = rem >> 2, c8 = rem & 3;
            uint32_t d = sbase + (uint32_t)(10240 + hl * 2560 + row * 40 + c8 * 8) * 2u;
            cp_async16(d, gW[hl] + row * GK + c * 32 + c8 * 8);
        }
        asm volatile("cp.async.commit_group;" ::: "memory");
    };

    float acc[2][4][4];
    #pragma unroll
    for (int mi = 0; mi < 2; mi++)
        #pragma unroll
        for (int ni = 0; ni < 4; ni++)
            #pragma unroll
            for (int r = 0; r < 4; r++) acc[mi][ni][r] = 0.f;

    const int arow  = lane & 15;
    const int akoff = (lane >> 4) * 8;
    const int bg    = lane >> 3;
    const int brow8 = lane & 7;

    issue_chunk(0);
    #pragma unroll 1
    for (int c = 0; c < 6; c++) {
        if (c + 1 < 6) {
            issue_chunk(c + 1);
            asm volatile("cp.async.wait_group 1;" ::: "memory");
        } else {
            asm volatile("cp.async.wait_group 0;" ::: "memory");
        }
        __syncthreads();

        const uint32_t sbase = sb + (uint32_t)(c & 1) * 30720u;
        #pragma unroll
        for (int ks = 0; ks < 2; ks++) {
            const int k0 = ks * 16;
            uint32_t ah[2][4], al[2][4], bh[4][2], bl[4][2];
            #pragma unroll
            for (int mi = 0; mi < 2; mi++) {
                uint32_t off = (uint32_t)((wm0 + mi * 16 + arow) * 40 + k0 + akoff) * 2u;
                LDSM_X4(ah[mi][0], ah[mi][1], ah[mi][2], ah[mi][3], sbase + off);
                LDSM_X4(al[mi][0], al[mi][1], al[mi][2], al[mi][3],
                        sbase + 5120u * 2u + off);
            }
            #pragma unroll
            for (int np = 0; np < 2; np++) {
                uint32_t off = (uint32_t)(10240
                    + (wn0 + (2 * np + (bg >> 1)) * 8 + brow8) * 40
                    + k0 + (bg & 1) * 8) * 2u;
                LDSM_X4(bh[2*np][0], bh[2*np][1], bh[2*np+1][0], bh[2*np+1][1],
                        sbase + off);
                LDSM_X4(bl[2*np][0], bl[2*np][1], bl[2*np+1][0], bl[2*np+1][1],
                        sbase + 2560u * 2u + off);
            }
            #pragma unroll
            for (int mi = 0; mi < 2; mi++)
                #pragma unroll
                for (int ni = 0; ni < 4; ni++)
                    MMA16816(acc[mi][ni], ah[mi], bh[ni]);
            #pragma unroll
            for (int mi = 0; mi < 2; mi++)
                #pragma unroll
                for (int ni = 0; ni < 4; ni++)
                    MMA16816(acc[mi][ni], ah[mi], bl[ni]);
            #pragma unroll
            for (int mi = 0; mi < 2; mi++)
                #pragma unroll
                for (int ni = 0; ni < 4; ni++)
                    MMA16816(acc[mi][ni], al[mi], bh[ni]);
        }
        __syncthreads();
    }

    float* C = Cm + (size_t)batch * NPIX * (size_t)Ntot;
    const int mr = lane >> 2, nc = (lane & 3) * 2;
    #pragma unroll
    for (int mi = 0; mi < 2; mi++)
        #pragma unroll
        for (int ni = 0; ni < 4; ni++) {
            const size_t m = bM + wm0 + mi * 16 + mr;
            const size_t n = (size_t)(bN + wn0 + ni * 8 + nc);
            float* a = acc[mi][ni];
            *(float2*)&C[m * Ntot + n]       = make_float2(a[0], a[1]);
            *(float2*)&C[(m + 8) * Ntot + n] = make_float2(a[2], a[3]);
        }
}

// ---------------------------------------------------------------------------
// proj GEMM (weight-major output):  C[b,m,n] = sum_k A[m,k] * B[b,n,k]
// (R9-proven kernel, unchanged: CTA 64Mx128N, six 32-chunks, pitch 40.)
// ---------------------------------------------------------------------------
__global__ __launch_bounds__(256) void gemm_mma(
    const unsigned short* __restrict__ Ahi,
    const unsigned short* __restrict__ Alo,
    const unsigned short* __restrict__ Bhi,
    const unsigned short* __restrict__ Blo,
    float* __restrict__ Cm, int Mtot)
{
    extern __shared__ __align__(16) unsigned short smem[];
    const int t = threadIdx.x, lane = t & 31, w = t >> 5;
    const int bM = blockIdx.x * 64;
    const size_t bN = (size_t)blockIdx.y * 128;
    const int batch = blockIdx.z;
    const int wm0 = (w >> 2) * 32;
    const int wn0 = (w & 3) * 32;

    const uint32_t sb = smem_u32(smem);
    const unsigned short* gA[2] = { Ahi + (size_t)bM * GK, Alo + (size_t)bM * GK };
    const size_t boff = ((size_t)batch * NPIX + bN) * GK;
    const unsigned short* gB[2] = { Bhi + boff, Blo + boff };

    auto issue_chunk = [&](int c) {
        const uint32_t sbase = sb + (uint32_t)(c & 1) * 30720u;
        #pragma unroll
        for (int i = 0; i < 2; i++) {
            int id = t + i * 256;
            int hl = id >> 8, rem = id & 255;
            int row = rem >> 2, c8 = rem & 3;
            uint32_t d = sbase + (uint32_t)(hl * 2560 + row * 40 + c8 * 8) * 2u;
            cp_async16(d, gA[hl] + row * GK + c * 32 + c8 * 8);
        }
        #pragma unroll
        for (int i = 0; i < 4; i++) {
            int id = t + i * 256;
            int hl = id >> 9, rem = id & 511;
            int row = rem >> 2, c8 = rem & 3;
            uint32_t d = sbase + (uint32_t)(5120 + hl * 5120 + row * 40 + c8 * 8) * 2u;
            cp_async16(d, gB[hl] + row * GK + c * 32 + c8 * 8);
        }
        asm volatile("cp.async.commit_group;" ::: "memory");
    };

    float acc[2][4][4];
    #pragma unroll
    for (int mi = 0; mi < 2; mi++)
        #pragma unroll
        for (int ni = 0; ni < 4; ni++)
            #pragma unroll
            for (int r = 0; r < 4; r++) acc[mi][ni][r] = 0.f;

    const int arow  = lane & 15;
    const int akoff = (lane >> 4) * 8;
    const int bg    = lane >> 3;
    const int brow8 = lane & 7;

    issue_chunk(0);
    #pragma unroll 1
    for (int c = 0; c < 6; c++) {
        if (c + 1 < 6) {
            issue_chunk(c + 1);
            asm volatile("cp.async.wait_group 1;" ::: "memory");
        } else {
            asm volatile("cp.async.wait_group 0;" ::: "memory");
        }
        __syncthreads();

        const uint32_t sbase = sb + (uint32_t)(c & 1) * 30720u;
        #pragma unroll
        for (int ks = 0; ks < 2; ks++) {
            const int k0 = ks * 16;
            uint32_t ah[2][4], al[2][4], bh[4][2], bl[4][2];
            #pragma unroll
            for (int mi = 0; mi < 2; mi++) {
                uint32_t off = (uint32_t)((wm0 + mi * 16 + arow) * 40 + k0 + akoff) * 2u;
                LDSM_X4(ah[mi][0], ah[mi][1], ah[mi][2], ah[mi][3], sbase + off);
                LDSM_X4(al[mi][0], al[mi][1], al[mi][2], al[mi][3],
                        sbase + 2560u * 2u + off);
            }
            #pragma unroll
            for (int np = 0; np < 2; np++) {
                uint32_t off = (uint32_t)(5120
                    + (wn0 + (2 * np + (bg >> 1)) * 8 + brow8) * 40
                    + k0 + (bg & 1) * 8) * 2u;
                LDSM_X4(bh[2*np][0], bh[2*np][1], bh[2*np+1][0], bh[2*np+1][1],
                        sbase + off);
                LDSM_X4(bl[2*np][0], bl[2*np][1], bl[2*np+1][0], bl[2*np+1][1],
                        sbase + 5120u * 2u + off);
            }
            #pragma unroll
            for (int mi = 0; mi < 2; mi++)
                #pragma unroll
                for (int ni = 0; ni < 4; ni++)
                    MMA16816(acc[mi][ni], ah[mi], bh[ni]);
            #pragma unroll
            for (int mi = 0; mi < 2; mi++)
                #pragma unroll
                for (int ni = 0; ni < 4; ni++)
                    MMA16816(acc[mi][ni], ah[mi], bl[ni]);
            #pragma unroll
            for (int mi = 0; mi < 2; mi++)
                #pragma unroll
                for (int ni = 0; ni < 4; ni++)
                    MMA16816(acc[mi][ni], al[mi], bh[ni]);
        }
        __syncthreads();
    }

    float* C = Cm + (size_t)batch * (size_t)Mtot * NPIX;
    const int mr = lane >> 2, nc = (lane & 3) * 2;
    #pragma unroll
    for (int mi = 0; mi < 2; mi++)
        #pragma unroll
        for (int ni = 0; ni < 4; ni++) {
            const size_t m = (size_t)(bM + wm0 + mi * 16 + mr);
            const size_t n = bN + wn0 + ni * 8 + nc;
            float* a = acc[mi][ni];
            *(float2*)&C[m * NPIX + n]       = make_float2(a[0], a[1]);
            *(float2*)&C[(m + 8) * NPIX + n] = make_float2(a[2], a[3]);
        }
}

// ---------------------------------------------------------------------------
// Fused depthwise-3x3 + 8x8-window channel attention.
// Reads pixel-major g_qkv [b][pix][576]: halo = 100 px x 6 float4 of channels
// per phase, perfectly coalesced (zero sector waste). Matmuls = R8-proven
// 256-thread tiles; fused bf16 transposed epilogue.
// ---------------------------------------------------------------------------
__global__ __launch_bounds__(256) void window_attn(
    const float* __restrict__ dww,    // [576*9]
    const float* __restrict__ tempr)  // [4]
{
    const int t    = threadIdx.x;
    const int head = blockIdx.x & 3;
    const int win  = blockIdx.x >> 2;
    const int b    = win >> 10;
    const int hn   = (win >> 5) & 31;
    const int wn   = win & 31;
    const int y0   = hn << 3, x0 = wn << 3;

    __shared__ float sq[48 * 64];
    __shared__ float skT[64 * 52];       // later reused as u32 staging [64][52]
    __shared__ float sv[48 * 64];
    __shared__ float scratch[2424];      // halo [24][101] -> attn [48][49]
    __shared__ float qin[48], kin[48];

    const size_t pixbase = (size_t)b * NPIX;

    // halo: 100 px x 24 ch = 600 float4-chunks per phase, 3 per thread
    float4 hreg4[3];
    auto load_halo = [&](int chbase) {
        #pragma unroll
        for (int i = 0; i < 3; i++) {
            int e = t + i * 256;
            float4 v = make_float4(0.f, 0.f, 0.f, 0.f);
            if (e < 600) {
                int px = e / 6, c4 = e - px * 6;
                int iy = px / 10, ix = px - iy * 10;
                int gy = y0 - 1 + iy, gx = x0 - 1 + ix;
                if ((unsigned)gy < 256u && (unsigned)gx < 256u)
                    v = *(const float4*)&g_qkv[
                        (pixbase + (size_t)gy * 256 + gx) * 576 + chbase + c4 * 4];
            }
            hreg4[i] = v;
        }
    };
    auto chbase_of = [&](int p) {
        return (p >> 1) * 192 + head * 48 + (p & 1) * 24;
    };

    load_halo(chbase_of(0));
    #pragma unroll 1
    for (int p = 0; p < 6; p++) {
        const int tensor = p >> 1;
        const int half   = p & 1;
        const int gch0   = tensor * 192 + head * 48 + half * 24;

        #pragma unroll
        for (int i = 0; i < 3; i++) {              // regs -> scratch [c][101]
            int e = t + i * 256;
            if (e < 600) {
                int px = e / 6, c4 = e - px * 6;
                int c = c4 * 4;
                scratch[(c + 0) * 101 + px] = hreg4[i].x;
                scratch[(c + 1) * 101 + px] = hreg4[i].y;
                scratch[(c + 2) * 101 + px] = hreg4[i].z;
                scratch[(c + 3) * 101 + px] = hreg4[i].w;
            }
        }
        __syncthreads();

        if (p < 5) load_halo(chbase_of(p + 1));

        #pragma unroll
        for (int u = 0; u < 6; u++) {
            int e  = t + u * 256;
            int c  = e >> 6;
            int pp = e & 63;
            int p1 = pp >> 3, p2 = pp & 7;
            const float* wr = dww + (gch0 + c) * 9;
            const float* tp = scratch + c * 101 + p1 * 10 + p2;
            float s = tp[ 0]*wr[0] + tp[ 1]*wr[1] + tp[ 2]*wr[2]
                    + tp[10]*wr[3] + tp[11]*wr[4] + tp[12]*wr[5]
                    + tp[20]*wr[6] + tp[21]*wr[7] + tp[22]*wr[8];
            int ch = half * 24 + c;
            if      (tensor == 0) sq[ch * 64 + pp]  = s;
            else if (tensor == 1) skT[pp * 52 + ch] = s;
            else                  sv[ch * 64 + pp]  = s;
        }
        __syncthreads();
    }

    if (t < 48) {
        float s = 0.f;
        #pragma unroll 8
        for (int d = 0; d < 64; d++) {
            float x = sq[t * 64 + ((d + t) & 63)];
            s = fmaf(x, x, s);
        }
        qin[t] = 1.f / fmaxf(sqrtf(s), 1e-12f);
    } else if (t >= 128 && t < 176) {
        int j = t - 128;
        float s = 0.f;
        #pragma unroll 8
        for (int d = 0; d < 64; d++) {
            float x = skT[d * 52 + j];
            s = fmaf(x, x, s);
        }
        kin[j] = 1.f / fmaxf(sqrtf(s), 1e-12f);
    }
    __syncthreads();

    float* sattn = scratch;
    const float tscale = __ldg(&tempr[head]);

    {
        const int ti = t >> 4;
        const int tj = t & 15;
        const int i0 = ti * 3, j0 = tj * 3;
        float acc[3][3];
        #pragma unroll
        for (int r = 0; r < 3; r++)
            #pragma unroll
            for (int s = 0; s < 3; s++) acc[r][s] = 0.f;

        for (int d0 = 0; d0 < 64; d0 += 4) {
            float4 qv[3];
            #pragma unroll
            for (int r = 0; r < 3; r++)
                qv[r] = *(const float4*)&sq[(i0 + r) * 64 + d0];
            #pragma unroll
            for (int dd = 0; dd < 4; dd++) {
                float kv[3];
                #pragma unroll
                for (int s = 0; s < 3; s++) kv[s] = skT[(d0 + dd) * 52 + j0 + s];
                #pragma unroll
                for (int r = 0; r < 3; r++) {
                    float qd = (dd == 0) ? qv[r].x : (dd == 1) ? qv[r].y
                             : (dd == 2) ? qv[r].z : qv[r].w;
                    #pragma unroll
                    for (int s = 0; s < 3; s++)
                        acc[r][s] = fmaf(qd, kv[s], acc[r][s]);
                }
            }
        }
        #pragma unroll
        for (int r = 0; r < 3; r++) {
            float qi = qin[i0 + r] * tscale;
            #pragma unroll
            for (int s = 0; s < 3; s++)
                sattn[(i0 + r) * 49 + j0 + s] = acc[r][s] * qi * kin[j0 + s];
        }
    }
    __syncthreads();

    if (t < 48) {
        float m = -1e30f;
        #pragma unroll 8
        for (int j = 0; j < 48; j++) m = fmaxf(m, sattn[t * 49 + j]);
        float s = 0.f;
        #pragma unroll 8
        for (int j = 0; j < 48; j++) {
            float e = __expf(sattn[t * 49 + j] - m);
            sattn[t * 49 + j] = e;
            s += e;
        }
        float inv = 1.f / s;
        #pragma unroll 8
        for (int j = 0; j < 48; j++) sattn[t * 49 + j] *= inv;
    }
    __syncthreads();

    // ---- out = attn @ v ; stage as packed bf16 (hi|lo) into skT (u32) ----
    uint32_t* stg = (uint32_t*)skT;                // [64 pix][52 ch]
    {
        const int td = t & 15;            // d0 = 4*td (pixel)
        const int ti = t >> 4;            // i0 = 3*ti (channel)
        const int d0 = td * 4, i0 = ti * 3;
        float acc[3][4];
        #pragma unroll
        for (int r = 0; r < 3; r++)
            #pragma unroll
            for (int s = 0; s < 4; s++) acc[r][s] = 0.f;

        for (int j = 0; j < 48; j++) {
            float4 vv = *(const float4*)&sv[j * 64 + d0];
            #pragma unroll
            for (int r = 0; r < 3; r++) {
                float a = sattn[(i0 + r) * 49 + j];
                acc[r][0] = fmaf(a, vv.x, acc[r][0]);
                acc[r][1] = fmaf(a, vv.y, acc[r][1]);
                acc[r][2] = fmaf(a, vv.z, acc[r][2]);
                acc[r][3] = fmaf(a, vv.w, acc[r][3]);
            }
        }
        __syncthreads();                           // skT reads done
        #pragma unroll
        for (int r = 0; r < 3; r++)
            #pragma unroll
            for (int s = 0; s < 4; s++) {
                float v = acc[r][s];
                __nv_bfloat16 h = __float2bfloat16(v);
                __nv_bfloat16 l = __float2bfloat16(v - __bfloat162float(h));
                stg[(d0 + s) * 52 + i0 + r] =
                    (uint32_t)*(unsigned short*)&h
                    | ((uint32_t)*(unsigned short*)&l << 16);
            }
    }
    __syncthreads();

    // cooperative transposed writeout: [pix][ch] -> g_bth/g_btl [b][pix][192]
    #pragma unroll
    for (int i = 0; i < 6; i++) {
        int id = t + i * 256;
        int row = id / 24, cp = id - row * 24;
        int c = cp * 2;
        uint32_t w0 = stg[row * 52 + c];
        uint32_t w1 = stg[row * 52 + c + 1];
        int p1 = row >> 3, p2 = row & 7;
        size_t o = (pixbase + (size_t)(y0 + p1) * 256 + (x0 + p2)) * GK
                 + head * 48 + c;
        *(ushort2*)&g_bth[o] = make_ushort2((unsigned short)w0, (unsigned short)w1);
        *(ushort2*)&g_btl[o] = make_ushort2((unsigned short)(w0 >> 16),
                                            (unsigned short)(w1 >> 16));
    }
}

// ---------------------------------------------------------------------------
extern "C" void kernel_launch(void* const* d_in, const int* in_sizes, int n_in,
                              void* d_out, int out_size)
{
    const float *x = nullptr, *qw = nullptr, *dw = nullptr, *pw = nullptr, *tp = nullptr;
    for (int i = 0; i < n_in; i++) {
        switch (in_sizes[i]) {
            case 25165824: x  = (const float*)d_in[i]; break;  // x [2,192,256,256]
            case 110592:   qw = (const float*)d_in[i]; break;  // qkv_w [576,192]
            case 5184:     dw = (const float*)d_in[i]; break;  // dw_w [576,1,3,3]
            case 36864:    pw = (const float*)d_in[i]; break;  // proj_w [192,192]
            case 4:        tp = (const float*)d_in[i]; break;  // temperature [4]
        }
    }

    void *qkvp, *bthp, *btlp, *wqhp, *wqlp, *wphp, *wplp;
    cudaGetSymbolAddress(&qkvp, g_qkv);
    cudaGetSymbolAddress(&bthp, g_bth);
    cudaGetSymbolAddress(&btlp, g_btl);
    cudaGetSymbolAddress(&wqhp, g_wqh);
    cudaGetSymbolAddress(&wqlp, g_wql);
    cudaGetSymbolAddress(&wphp, g_wph);
    cudaGetSymbolAddress(&wplp, g_wpl);

    const int GEMM_SMEM = 2 * 30720;             // 61440 B -> 3 CTAs/SM
    cudaFuncSetAttribute(gemm_nt,  cudaFuncAttributeMaxDynamicSharedMemorySize, GEMM_SMEM);
    cudaFuncSetAttribute(gemm_mma, cudaFuncAttributeMaxDynamicSharedMemorySize, GEMM_SMEM);

    wconvert<<<(110592 + 255) / 256, 256>>>(qw, 110592,
        (unsigned short*)wqhp, (unsigned short*)wqlp);
    wconvert<<<(36864 + 255) / 256, 256>>>(pw, 36864,
        (unsigned short*)wphp, (unsigned short*)wplp);

    // 1) x -> x^T bf16 hi/lo  ([b][pix][192])
    convtrans<<<dim3(2048, 6, 2), 256>>>(x,
        (unsigned short*)bthp, (unsigned short*)btlp);

    // 2) qkv GEMM, pixel-major output: g_qkv[b][pix][576]
    //    (grid.x = och tiles, fastest -> A pixel-tiles L2-resident across them)
    gemm_nt<<<dim3(9, 512, 2), 256, GEMM_SMEM>>>(
        (const unsigned short*)bthp, (const unsigned short*)btlp,
        (const unsigned short*)wqhp, (const unsigned short*)wqlp,
        (float*)qkvp, 576);

    // 3) fused depthwise 3x3 + attention (coalesced pixel-major halo reads);
    //    writes bf16 hi/lo transposed into g_bth/g_btl
    window_attn<<<8192, 256>>>(dw, tp);

    // 4) proj GEMM -> d_out ([b][192][65536], ch-major)
    gemm_mma<<<dim3(3, 512, 2), 256, GEMM_SMEM>>>(
        (const unsigned short*)wphp, (const unsigned short*)wplp,
        (const unsigned short*)bthp, (const unsigned short*)btlp,
        (float*)d_out, 192);
}

// round 11
// speedup vs baseline: 1.2362x; 1.1375x over previous
#include <cuda_runtime.h>
#include <cuda_bf16.h>
#include <cstdint>

#define GK   192
#define NPIX 65536

// ---------------------------------------------------------------------------
// scratch (allocation-free rule: __device__ globals)
// ---------------------------------------------------------------------------
__device__ float g_qkv[75497472];                         // [2][65536][576] f32 (pixel-major)
__device__ __align__(16) unsigned short g_bth[25165824];  // [2][65536][192] bf16 hi
__device__ __align__(16) unsigned short g_btl[25165824];  // [2][65536][192] bf16 lo
__device__ __align__(16) unsigned short g_wqh[110592], g_wql[110592];
__device__ __align__(16) unsigned short g_wph[36864],  g_wpl[36864];

// ---------------------------------------------------------------------------
__device__ __forceinline__ uint32_t smem_u32(const void* p) {
    uint32_t a;
    asm("{ .reg .u64 t; cvta.to.shared.u64 t, %1; cvt.u32.u64 %0, t; }"
        : "=r"(a) : "l"(p));
    return a;
}

__device__ __forceinline__ void cp_async16(uint32_t dst, const void* src) {
    asm volatile("cp.async.cg.shared.global [%0], [%1], 16;"
                 :: "r"(dst), "l"(src) : "memory");
}

#define LDSM_X4(r0, r1, r2, r3, a) \
    asm volatile("ldmatrix.sync.aligned.m8n8.x4.shared.b16 {%0,%1,%2,%3}, [%4];" \
                 : "=r"(r0), "=r"(r1), "=r"(r2), "=r"(r3) : "r"(a))

#define MMA16816(d, a, b) \
    asm volatile("mma.sync.aligned.m16n8k16.row.col.f32.bf16.bf16.f32 " \
                 "{%0,%1,%2,%3}, {%4,%5,%6,%7}, {%8,%9}, {%0,%1,%2,%3};" \
                 : "+f"((d)[0]), "+f"((d)[1]), "+f"((d)[2]), "+f"((d)[3]) \
                 : "r"((a)[0]), "r"((a)[1]), "r"((a)[2]), "r"((a)[3]), \
                   "r"((b)[0]), "r"((b)[1]))

// ---------------------------------------------------------------------------
// convert + transpose: src f32 [2][192][65536] -> dhi/dlo bf16 [2][65536][192]
// ---------------------------------------------------------------------------
__global__ __launch_bounds__(256) void convtrans(
    const float* __restrict__ src,
    unsigned short* __restrict__ dhi,
    unsigned short* __restrict__ dlo)
{
    __shared__ float sm[32][33];
    const int p0 = blockIdx.x * 32, c0 = blockIdx.y * 32, b = blockIdx.z;
    const float* s = src + (size_t)b * GK * NPIX;
    const int tc = threadIdx.x & 31, tr = threadIdx.x >> 5;

    #pragma unroll
    for (int i = 0; i < 4; i++) {
        int cl = tr + i * 8;
        sm[cl][tc] = s[(size_t)(c0 + cl) * NPIX + p0 + tc];
    }
    __syncthreads();

    const size_t obase = (size_t)b * NPIX * GK;
    #pragma unroll
    for (int i = 0; i < 4; i++) {
        int pl = tr + i * 8;
        float v = sm[tc][pl];
        __nv_bfloat16 h = __float2bfloat16(v);
        __nv_bfloat16 l = __float2bfloat16(v - __bfloat162float(h));
        size_t o = obase + (size_t)(p0 + pl) * GK + c0 + tc;
        dhi[o] = *(unsigned short*)&h;
        dlo[o] = *(unsigned short*)&l;
    }
}

__global__ void wconvert(const float* __restrict__ w, int n,
                         unsigned short* __restrict__ hi,
                         unsigned short* __restrict__ lo)
{
    int i = blockIdx.x * 256 + threadIdx.x;
    if (i < n) {
        float v = w[i];
        __nv_bfloat16 h = __float2bfloat16(v);
        __nv_bfloat16 l = __float2bfloat16(v - __bfloat162float(h));
        hi[i] = *(unsigned short*)&h;
        lo[i] = *(unsigned short*)&l;
    }
}

// ---------------------------------------------------------------------------
// qkv GEMM, pixel-major output (unchanged from R10)
// ---------------------------------------------------------------------------
__global__ __launch_bounds__(256) void gemm_nt(
    const unsigned short* __restrict__ Ahi,
    const unsigned short* __restrict__ Alo,
    const unsigned short* __restrict__ Whi,
    const unsigned short* __restrict__ Wlo,
    float* __restrict__ Cm, int Ntot)
{
    extern __shared__ __align__(16) unsigned short smem[];
    const int t = threadIdx.x, lane = t & 31, w = t >> 5;
    const int bN = blockIdx.x * 64;
    const size_t bM = (size_t)blockIdx.y * 128;
    const int batch = blockIdx.z;
    const int wm0 = (w & 3) * 32;
    const int wn0 = (w >> 2) * 32;

    const uint32_t sb = smem_u32(smem);
    const size_t aoff = ((size_t)batch * NPIX + bM) * GK;
    const unsigned short* gA[2] = { Ahi + aoff, Alo + aoff };
    const unsigned short* gW[2] = { Whi + (size_t)bN * GK, Wlo + (size_t)bN * GK };

    auto issue_chunk = [&](int c) {
        const uint32_t sbase = sb + (uint32_t)(c & 1) * 30720u;
        #pragma unroll
        for (int i = 0; i < 4; i++) {
            int id = t + i * 256;
            int hl = id >> 9, rem = id & 511;
            int row = rem >> 2, c8 = rem & 3;
            uint32_t d = sbase + (uint32_t)(hl * 5120 + row * 40 + c8 * 8) * 2u;
            cp_async16(d, gA[hl] + row * GK + c * 32 + c8 * 8);
        }
        #pragma unroll
        for (int i = 0; i < 2; i++) {
            int id = t + i * 256;
            int hl = id >> 8, rem = id & 255;
            int row = rem >> 2, c8 = rem & 3;
            uint32_t d = sbase + (uint32_t)(10240 + hl * 2560 + row * 40 + c8 * 8) * 2u;
            cp_async16(d, gW[hl] + row * GK + c * 32 + c8 * 8);
        }
        asm volatile("cp.async.commit_group;" ::: "memory");
    };

    float acc[2][4][4];
    #pragma unroll
    for (int mi = 0; mi < 2; mi++)
        #pragma unroll
        for (int ni = 0; ni < 4; ni++)
            #pragma unroll
            for (int r = 0; r < 4; r++) acc[mi][ni][r] = 0.f;

    const int arow  = lane & 15;
    const int akoff = (lane >> 4) * 8;
    const int bg    = lane >> 3;
    const int brow8 = lane & 7;

    issue_chunk(0);
    #pragma unroll 1
    for (int c = 0; c < 6; c++) {
        if (c + 1 < 6) {
            issue_chunk(c + 1);
            asm volatile("cp.async.wait_group 1;" ::: "memory");
        } else {
            asm volatile("cp.async.wait_group 0;" ::: "memory");
        }
        __syncthreads();

        const uint32_t sbase = sb + (uint32_t)(c & 1) * 30720u;
        #pragma unroll
        for (int ks = 0; ks < 2; ks++) {
            const int k0 = ks * 16;
            uint32_t ah[2][4], al[2][4], bh[4][2], bl[4][2];
            #pragma unroll
            for (int mi = 0; mi < 2; mi++) {
                uint32_t off = (uint32_t)((wm0 + mi * 16 + arow) * 40 + k0 + akoff) * 2u;
                LDSM_X4(ah[mi][0], ah[mi][1], ah[mi][2], ah[mi][3], sbase + off);
                LDSM_X4(al[mi][0], al[mi][1], al[mi][2], al[mi][3],
                        sbase + 5120u * 2u + off);
            }
            #pragma unroll
            for (int np = 0; np < 2; np++) {
                uint32_t off = (uint32_t)(10240
                    + (wn0 + (2 * np + (bg >> 1)) * 8 + brow8) * 40
                    + k0 + (bg & 1) * 8) * 2u;
                LDSM_X4(bh[2*np][0], bh[2*np][1], bh[2*np+1][0], bh[2*np+1][1],
                        sbase + off);
                LDSM_X4(bl[2*np][0], bl[2*np][1], bl[2*np+1][0], bl[2*np+1][1],
                        sbase + 2560u * 2u + off);
            }
            #pragma unroll
            for (int mi = 0; mi < 2; mi++)
                #pragma unroll
                for (int ni = 0; ni < 4; ni++)
                    MMA16816(acc[mi][ni], ah[mi], bh[ni]);
            #pragma unroll
            for (int mi = 0; mi < 2; mi++)
                #pragma unroll
                for (int ni = 0; ni < 4; ni++)
                    MMA16816(acc[mi][ni], ah[mi], bl[ni]);
            #pragma unroll
            for (int mi = 0; mi < 2; mi++)
                #pragma unroll
                for (int ni = 0; ni < 4; ni++)
                    MMA16816(acc[mi][ni], al[mi], bh[ni]);
        }
        __syncthreads();
    }

    float* C = Cm + (size_t)batch * NPIX * (size_t)Ntot;
    const int mr = lane >> 2, nc = (lane & 3) * 2;
    #pragma unroll
    for (int mi = 0; mi < 2; mi++)
        #pragma unroll
        for (int ni = 0; ni < 4; ni++) {
            const size_t m = bM + wm0 + mi * 16 + mr;
            const size_t n = (size_t)(bN + wn0 + ni * 8 + nc);
            float* a = acc[mi][ni];
            *(float2*)&C[m * Ntot + n]       = make_float2(a[0], a[1]);
            *(float2*)&C[(m + 8) * Ntot + n] = make_float2(a[2], a[3]);
        }
}

// ---------------------------------------------------------------------------
// proj GEMM (unchanged from R10)
// ---------------------------------------------------------------------------
__global__ __launch_bounds__(256) void gemm_mma(
    const unsigned short* __restrict__ Ahi,
    const unsigned short* __restrict__ Alo,
    const unsigned short* __restrict__ Bhi,
    const unsigned short* __restrict__ Blo,
    float* __restrict__ Cm, int Mtot)
{
    extern __shared__ __align__(16) unsigned short smem[];
    const int t = threadIdx.x, lane = t & 31, w = t >> 5;
    const int bM = blockIdx.x * 64;
    const size_t bN = (size_t)blockIdx.y * 128;
    const int batch = blockIdx.z;
    const int wm0 = (w >> 2) * 32;
    const int wn0 = (w & 3) * 32;

    const uint32_t sb = smem_u32(smem);
    const unsigned short* gA[2] = { Ahi + (size_t)bM * GK, Alo + (size_t)bM * GK };
    const size_t boff = ((size_t)batch * NPIX + bN) * GK;
    const unsigned short* gB[2] = { Bhi + boff, Blo + boff };

    auto issue_chunk = [&](int c) {
        const uint32_t sbase = sb + (uint32_t)(c & 1) * 30720u;
        #pragma unroll
        for (int i = 0; i < 2; i++) {
            int id = t + i * 256;
            int hl = id >> 8, rem = id & 255;
            int row = rem >> 2, c8 = rem & 3;
            uint32_t d = sbase + (uint32_t)(hl * 2560 + row * 40 + c8 * 8) * 2u;
            cp_async16(d, gA[hl] + row * GK + c * 32 + c8 * 8);
        }
        #pragma unroll
        for (int i = 0; i < 4; i++) {
            int id = t + i * 256;
            int hl = id >> 9, rem = id & 511;
            int row = rem >> 2, c8 = rem & 3;
            uint32_t d = sbase + (uint32_t)(5120 + hl * 5120 + row * 40 + c8 * 8) * 2u;
            cp_async16(d, gB[hl] + row * GK + c * 32 + c8 * 8);
        }
        asm volatile("cp.async.commit_group;" ::: "memory");
    };

    float acc[2][4][4];
    #pragma unroll
    for (int mi = 0; mi < 2; mi++)
        #pragma unroll
        for (int ni = 0; ni < 4; ni++)
            #pragma unroll
            for (int r = 0; r < 4; r++) acc[mi][ni][r] = 0.f;

    const int arow  = lane & 15;
    const int akoff = (lane >> 4) * 8;
    const int bg    = lane >> 3;
    const int brow8 = lane & 7;

    issue_chunk(0);
    #pragma unroll 1
    for (int c = 0; c < 6; c++) {
        if (c + 1 < 6) {
            issue_chunk(c + 1);
            asm volatile("cp.async.wait_group 1;" ::: "memory");
        } else {
            asm volatile("cp.async.wait_group 0;" ::: "memory");
        }
        __syncthreads();

        const uint32_t sbase = sb + (uint32_t)(c & 1) * 30720u;
        #pragma unroll
        for (int ks = 0; ks < 2; ks++) {
            const int k0 = ks * 16;
            uint32_t ah[2][4], al[2][4], bh[4][2], bl[4][2];
            #pragma unroll
            for (int mi = 0; mi < 2; mi++) {
                uint32_t off = (uint32_t)((wm0 + mi * 16 + arow) * 40 + k0 + akoff) * 2u;
                LDSM_X4(ah[mi][0], ah[mi][1], ah[mi][2], ah[mi][3], sbase + off);
                LDSM_X4(al[mi][0], al[mi][1], al[mi][2], al[mi][3],
                        sbase + 2560u * 2u + off);
            }
            #pragma unroll
            for (int np = 0; np < 2; np++) {
                uint32_t off = (uint32_t)(5120
                    + (wn0 + (2 * np + (bg >> 1)) * 8 + brow8) * 40
                    + k0 + (bg & 1) * 8) * 2u;
                LDSM_X4(bh[2*np][0], bh[2*np][1], bh[2*np+1][0], bh[2*np+1][1],
                        sbase + off);
                LDSM_X4(bl[2*np][0], bl[2*np][1], bl[2*np+1][0], bl[2*np+1][1],
                        sbase + 5120u * 2u + off);
            }
            #pragma unroll
            for (int mi = 0; mi < 2; mi++)
                #pragma unroll
                for (int ni = 0; ni < 4; ni++)
                    MMA16816(acc[mi][ni], ah[mi], bh[ni]);
            #pragma unroll
            for (int mi = 0; mi < 2; mi++)
                #pragma unroll
                for (int ni = 0; ni < 4; ni++)
                    MMA16816(acc[mi][ni], ah[mi], bl[ni]);
            #pragma unroll
            for (int mi = 0; mi < 2; mi++)
                #pragma unroll
                for (int ni = 0; ni < 4; ni++)
                    MMA16816(acc[mi][ni], al[mi], bh[ni]);
        }
        __syncthreads();
    }

    float* C = Cm + (size_t)batch * (size_t)Mtot * NPIX;
    const int mr = lane >> 2, nc = (lane & 3) * 2;
    #pragma unroll
    for (int mi = 0; mi < 2; mi++)
        #pragma unroll
        for (int ni = 0; ni < 4; ni++) {
            const size_t m = (size_t)(bM + wm0 + mi * 16 + mr);
            const size_t n = bN + wn0 + ni * 8 + nc;
            float* a = acc[mi][ni];
            *(float2*)&C[m * NPIX + n]       = make_float2(a[0], a[1]);
            *(float2*)&C[(m + 8) * NPIX + n] = make_float2(a[2], a[3]);
        }
}

// ---------------------------------------------------------------------------
// Fused depthwise-3x3 + window channel attention, full float4 datapaths.
// Dynamic smem (50.3 KB): sq[48*64] | skT[64*52] | sv[48*64] |
//   scratch[2800] (halo [100][28] pixel-major -> sattn [48][52]) |
//   w4s[216] ([9][24] transposed weights) | qin[48] | kin[48]
// ---------------------------------------------------------------------------
#define ATTN_SMEM_FLOATS (3072 + 3328 + 3072 + 2800 + 216 + 48 + 48)
__global__ __launch_bounds__(256) void window_attn(
    const float* __restrict__ dww,    // [576*9]
    const float* __restrict__ tempr)  // [4]
{
    extern __shared__ __align__(16) float dsm[];
    float* sq      = dsm;              // [48 ch][64 px]
    float* skT     = dsm + 3072;       // [64 px][52 ch]
    float* sv      = dsm + 6400;       // [48 ch][64 px]
    float* scratch = dsm + 9472;       // halo [100][28] -> sattn [48][52]
    float* w4s     = dsm + 12272;      // [9][24]
    float* qin     = dsm + 12488;
    float* kin     = dsm + 12536;

    const int t    = threadIdx.x;
    const int head = blockIdx.x & 3;
    const int win  = blockIdx.x >> 2;
    const int b    = win >> 10;
    const int hn   = (win >> 5) & 31;
    const int wn   = win & 31;
    const int y0   = hn << 3, x0 = wn << 3;

    const size_t pixbase = (size_t)b * NPIX;

    // halo: 100 px x 24 ch = 600 float4-chunks per phase, 3 per thread
    float4 hreg4[3];
    auto load_halo = [&](int chbase) {
        #pragma unroll
        for (int i = 0; i < 3; i++) {
            int e = t + i * 256;
            float4 v = make_float4(0.f, 0.f, 0.f, 0.f);
            if (e < 600) {
                int px = e / 6, c4 = e - px * 6;
                int iy = px / 10, ix = px - iy * 10;
                int gy = y0 - 1 + iy, gx = x0 - 1 + ix;
                if ((unsigned)gy < 256u && (unsigned)gx < 256u)
                    v = *(const float4*)&g_qkv[
                        (pixbase + (size_t)gy * 256 + gx) * 576 + chbase + c4 * 4];
            }
            hreg4[i] = v;
        }
    };
    auto chbase_of = [&](int p) {
        return (p >> 1) * 192 + head * 48 + (p & 1) * 24;
    };

    load_halo(chbase_of(0));
    #pragma unroll 1
    for (int p = 0; p < 6; p++) {
        const int tensor = p >> 1;
        const int half   = p & 1;
        const int gch0   = tensor * 192 + head * 48 + half * 24;

        // stage transposed weights [9][24] for this phase
        if (t < 216) {
            int k = t / 24, c = t - k * 24;
            w4s[k * 24 + c] = dww[(gch0 + c) * 9 + k];
        }
        // halo regs -> scratch pixel-major [100][28]
        #pragma unroll
        for (int i = 0; i < 3; i++) {
            int e = t + i * 256;
            if (e < 600) {
                int px = e / 6, c4 = e - px * 6;
                *(float4*)&scratch[px * 28 + c4 * 4] = hreg4[i];
            }
        }
        __syncthreads();

        if (p < 5) load_halo(chbase_of(p + 1));

        // conv: 64 px x 6 c4-groups = 384 float4 tasks
        #pragma unroll
        for (int g = 0; g < 2; g++) {
            int task = t + g * 256;
            if (task < 384) {
                int px = task & 63, c4g = task >> 6;
                int p1 = px >> 3, p2 = px & 7;
                const float* hb = scratch + (p1 * 10 + p2) * 28 + c4g * 4;
                float4 acc = make_float4(0.f, 0.f, 0.f, 0.f);
                #pragma unroll
                for (int k = 0; k < 9; k++) {
                    const int dy = k / 3, dx = k - (k / 3) * 3;
                    float4 h = *(const float4*)&hb[(dy * 10 + dx) * 28];
                    float4 wv = *(const float4*)&w4s[k * 24 + c4g * 4];
                    acc.x = fmaf(h.x, wv.x, acc.x);
                    acc.y = fmaf(h.y, wv.y, acc.y);
                    acc.z = fmaf(h.z, wv.z, acc.z);
                    acc.w = fmaf(h.w, wv.w, acc.w);
                }
                int ch = half * 24 + c4g * 4;
                if (tensor == 0) {
                    sq[(ch + 0) * 64 + px] = acc.x;
                    sq[(ch + 1) * 64 + px] = acc.y;
                    sq[(ch + 2) * 64 + px] = acc.z;
                    sq[(ch + 3) * 64 + px] = acc.w;
                } else if (tensor == 1) {
                    *(float4*)&skT[px * 52 + ch] = acc;
                } else {
                    sv[(ch + 0) * 64 + px] = acc.x;
                    sv[(ch + 1) * 64 + px] = acc.y;
                    sv[(ch + 2) * 64 + px] = acc.z;
                    sv[(ch + 3) * 64 + px] = acc.w;
                }
            }
        }
        __syncthreads();
    }

    // ---- l2 norms ----
    if (t < 48) {
        float s = 0.f;
        #pragma unroll 8
        for (int d = 0; d < 64; d++) {
            float x = sq[t * 64 + ((d + t) & 63)];
            s = fmaf(x, x, s);
        }
        qin[t] = 1.f / fmaxf(sqrtf(s), 1e-12f);
    } else if (t >= 128 && t < 176) {
        int j = t - 128;
        float s = 0.f;
        #pragma unroll 8
        for (int d = 0; d < 64; d++) {
            float x = skT[d * 52 + j];
            s = fmaf(x, x, s);
        }
        kin[j] = 1.f / fmaxf(sqrtf(s), 1e-12f);
    }
    __syncthreads();

    float* sattn = scratch;                        // [48][52]
    const float tscale = __ldg(&tempr[head]);

    // ---- logits: 192 threads, 3i x 4j tile, kv via LDS.128 ----
    if (t < 192) {
        const int ti = t / 12, tj = t - ti * 12;
        const int i0 = ti * 3, j0 = tj * 4;
        float acc[3][4];
        #pragma unroll
        for (int r = 0; r < 3; r++)
            #pragma unroll
            for (int s = 0; s < 4; s++) acc[r][s] = 0.f;

        for (int d0 = 0; d0 < 64; d0 += 4) {
            float4 qv[3];
            #pragma unroll
            for (int r = 0; r < 3; r++)
                qv[r] = *(const float4*)&sq[(i0 + r) * 64 + d0];
            #pragma unroll
            for (int dd = 0; dd < 4; dd++) {
                float4 kv = *(const float4*)&skT[(d0 + dd) * 52 + j0];
                #pragma unroll
                for (int r = 0; r < 3; r++) {
                    float qd = (dd == 0) ? qv[r].x : (dd == 1) ? qv[r].y
                             : (dd == 2) ? qv[r].z : qv[r].w;
                    acc[r][0] = fmaf(qd, kv.x, acc[r][0]);
                    acc[r][1] = fmaf(qd, kv.y, acc[r][1]);
                    acc[r][2] = fmaf(qd, kv.z, acc[r][2]);
                    acc[r][3] = fmaf(qd, kv.w, acc[r][3]);
                }
            }
        }
        float k0s = kin[j0], k1s = kin[j0 + 1], k2s = kin[j0 + 2], k3s = kin[j0 + 3];
        #pragma unroll
        for (int r = 0; r < 3; r++) {
            float qi = qin[i0 + r] * tscale;
            *(float4*)&sattn[(i0 + r) * 52 + j0] = make_float4(
                acc[r][0] * qi * k0s, acc[r][1] * qi * k1s,
                acc[r][2] * qi * k2s, acc[r][3] * qi * k3s);
        }
    }
    __syncthreads();

    // ---- softmax over j (48 threads, float4 rows) ----
    if (t < 48) {
        float4 row[12];
        float m = -1e30f;
        #pragma unroll
        for (int jg = 0; jg < 12; jg++) {
            row[jg] = *(const float4*)&sattn[t * 52 + jg * 4];
            m = fmaxf(m, fmaxf(fmaxf(row[jg].x, row[jg].y),
                               fmaxf(row[jg].z, row[jg].w)));
        }
        float s = 0.f;
        #pragma unroll
        for (int jg = 0; jg < 12; jg++) {
            row[jg].x = __expf(row[jg].x - m);
            row[jg].y = __expf(row[jg].y - m);
            row[jg].z = __expf(row[jg].z - m);
            row[jg].w = __expf(row[jg].w - m);
            s += row[jg].x + row[jg].y + row[jg].z + row[jg].w;
        }
        float inv = 1.f / s;
        #pragma unroll
        for (int jg = 0; jg < 12; jg++) {
            row[jg].x *= inv; row[jg].y *= inv;
            row[jg].z *= inv; row[jg].w *= inv;
            *(float4*)&sattn[t * 52 + jg * 4] = row[jg];
        }
    }
    __syncthreads();

    // ---- out = attn @ v ; 3i x 4d tile, attn rows via LDS.128 ----
    uint32_t* stg = (uint32_t*)skT;                // [64 px][52 ch]
    {
        const int td = t & 15;            // d0 = 4*td (pixel)
        const int ti = t >> 4;            // i0 = 3*ti (channel)
        const int d0 = td * 4, i0 = ti * 3;
        float acc[3][4];
        #pragma unroll
        for (int r = 0; r < 3; r++)
            #pragma unroll
            for (int s = 0; s < 4; s++) acc[r][s] = 0.f;

        #pragma unroll 2
        for (int jg = 0; jg < 12; jg++) {
            const int j = jg * 4;
            float4 a0 = *(const float4*)&sattn[(i0 + 0) * 52 + j];
            float4 a1 = *(const float4*)&sattn[(i0 + 1) * 52 + j];
            float4 a2 = *(const float4*)&sattn[(i0 + 2) * 52 + j];
            float4 v0 = *(const float4*)&sv[(j + 0) * 64 + d0];
            float4 v1 = *(const float4*)&sv[(j + 1) * 64 + d0];
            float4 v2 = *(const float4*)&sv[(j + 2) * 64 + d0];
            float4 v3 = *(const float4*)&sv[(j + 3) * 64 + d0];
            #pragma unroll
            for (int r = 0; r < 3; r++) {
                float4 a = (r == 0) ? a0 : (r == 1) ? a1 : a2;
                acc[r][0] = fmaf(a.x, v0.x, acc[r][0]);
                acc[r][1] = fmaf(a.x, v0.y, acc[r][1]);
                acc[r][2] = fmaf(a.x, v0.z, acc[r][2]);
                acc[r][3] = fmaf(a.x, v0.w, acc[r][3]);
                acc[r][0] = fmaf(a.y, v1.x, acc[r][0]);
                acc[r][1] = fmaf(a.y, v1.y, acc[r][1]);
                acc[r][2] = fmaf(a.y, v1.z, acc[r][2]);
                acc[r][3] = fmaf(a.y, v1.w, acc[r][3]);
                acc[r][0] = fmaf(a.z, v2.x, acc[r][0]);
                acc[r][1] = fmaf(a.z, v2.y, acc[r][1]);
                acc[r][2] = fmaf(a.z, v2.z, acc[r][2]);
                acc[r][3] = fmaf(a.z, v2.w, acc[r][3]);
                acc[r][0] = fmaf(a.w, v3.x, acc[r][0]);
                acc[r][1] = fmaf(a.w, v3.y, acc[r][1]);
                acc[r][2] = fmaf(a.w, v3.z, acc[r][2]);
                acc[r][3] = fmaf(a.w, v3.w, acc[r][3]);
            }
        }
        __syncthreads();                           // skT readers done
        #pragma unroll
        for (int r = 0; r < 3; r++)
            #pragma unroll
            for (int s = 0; s < 4; s++) {
                float v = acc[r][s];
                __nv_bfloat16 h = __float2bfloat16(v);
                __nv_bfloat16 l = __float2bfloat16(v - __bfloat162float(h));
                stg[(d0 + s) * 52 + i0 + r] =
                    (uint32_t)*(unsigned short*)&h
                    | ((uint32_t)*(unsigned short*)&l << 16);
            }
    }
    __syncthreads();

    // cooperative transposed writeout -> g_bth/g_btl [b][pix][192]
    #pragma unroll
    for (int i = 0; i < 6; i++) {
        int id = t + i * 256;
        int row = id / 24, cp = id - row * 24;
        int c = cp * 2;
        uint32_t w0 = stg[row * 52 + c];
        uint32_t w1 = stg[row * 52 + c + 1];
        int p1 = row >> 3, p2 = row & 7;
        size_t o = (pixbase + (size_t)(y0 + p1) * 256 + (x0 + p2)) * GK
                 + head * 48 + c;
        *(ushort2*)&g_bth[o] = make_ushort2((unsigned short)w0, (unsigned short)w1);
        *(ushort2*)&g_btl[o] = make_ushort2((unsigned short)(w0 >> 16),
                                            (unsigned short)(w1 >> 16));
    }
}

// ---------------------------------------------------------------------------
extern "C" void kernel_launch(void* const* d_in, const int* in_sizes, int n_in,
                              void* d_out, int out_size)
{
    const float *x = nullptr, *qw = nullptr, *dw = nullptr, *pw = nullptr, *tp = nullptr;
    for (int i = 0; i < n_in; i++) {
        switch (in_sizes[i]) {
            case 25165824: x  = (const float*)d_in[i]; break;  // x [2,192,256,256]
            case 110592:   qw = (const float*)d_in[i]; break;  // qkv_w [576,192]
            case 5184:     dw = (const float*)d_in[i]; break;  // dw_w [576,1,3,3]
            case 36864:    pw = (const float*)d_in[i]; break;  // proj_w [192,192]
            case 4:        tp = (const float*)d_in[i]; break;  // temperature [4]
        }
    }

    void *qkvp, *bthp, *btlp, *wqhp, *wqlp, *wphp, *wplp;
    cudaGetSymbolAddress(&qkvp, g_qkv);
    cudaGetSymbolAddress(&bthp, g_bth);
    cudaGetSymbolAddress(&btlp, g_btl);
    cudaGetSymbolAddress(&wqhp, g_wqh);
    cudaGetSymbolAddress(&wqlp, g_wql);
    cudaGetSymbolAddress(&wphp, g_wph);
    cudaGetSymbolAddress(&wplp, g_wpl);

    const int GEMM_SMEM = 2 * 30720;               // 61440 B -> 3 CTAs/SM
    const int ATTN_SMEM = ATTN_SMEM_FLOATS * 4;    // 50336 B -> 4 CTAs/SM
    cudaFuncSetAttribute(gemm_nt,  cudaFuncAttributeMaxDynamicSharedMemorySize, GEMM_SMEM);
    cudaFuncSetAttribute(gemm_mma, cudaFuncAttributeMaxDynamicSharedMemorySize, GEMM_SMEM);
    cudaFuncSetAttribute(window_attn, cudaFuncAttributeMaxDynamicSharedMemorySize, ATTN_SMEM);

    wconvert<<<(110592 + 255) / 256, 256>>>(qw, 110592,
        (unsigned short*)wqhp, (unsigned short*)wqlp);
    wconvert<<<(36864 + 255) / 256, 256>>>(pw, 36864,
        (unsigned short*)wphp, (unsigned short*)wplp);

    // 1) x -> x^T bf16 hi/lo  ([b][pix][192])
    convtrans<<<dim3(2048, 6, 2), 256>>>(x,
        (unsigned short*)bthp, (unsigned short*)btlp);

    // 2) qkv GEMM, pixel-major output: g_qkv[b][pix][576]
    gemm_nt<<<dim3(9, 512, 2), 256, GEMM_SMEM>>>(
        (const unsigned short*)bthp, (const unsigned short*)btlp,
        (const unsigned short*)wqhp, (const unsigned short*)wqlp,
        (float*)qkvp, 576);

    // 3) fused depthwise 3x3 + attention; writes bf16 hi/lo transposed
    window_attn<<<8192, 256, ATTN_SMEM>>>(dw, tp);

    // 4) proj GEMM -> d_out ([b][192][65536], ch-major)
    gemm_mma<<<dim3(3, 512, 2), 256, GEMM_SMEM>>>(
        (const unsigned short*)wphp, (const unsigned short*)wplp,
        (const unsigned short*)bthp, (const unsigned short*)btlp,
        (float*)d_out, 192);
}

// round 12
// speedup vs baseline: 1.2671x; 1.0250x over previous
#include <cuda_runtime.h>
#include <cuda_bf16.h>
#include <cstdint>

#define GK   192
#define NPIX 65536

// ---------------------------------------------------------------------------
// scratch (allocation-free rule: __device__ globals)
// ---------------------------------------------------------------------------
__device__ float g_qkv[75497472];                         // [2][65536][576] f32 (pixel-major)
__device__ __align__(16) unsigned short g_bth[25165824];  // [2][65536][192] bf16 hi
__device__ __align__(16) unsigned short g_btl[25165824];  // [2][65536][192] bf16 lo
__device__ __align__(16) unsigned short g_wqh[110592], g_wql[110592];
__device__ __align__(16) unsigned short g_wph[36864],  g_wpl[36864];

// ---------------------------------------------------------------------------
__device__ __forceinline__ uint32_t smem_u32(const void* p) {
    uint32_t a;
    asm("{ .reg .u64 t; cvta.to.shared.u64 t, %1; cvt.u32.u64 %0, t; }"
        : "=r"(a) : "l"(p));
    return a;
}

__device__ __forceinline__ void cp_async16(uint32_t dst, const void* src) {
    asm volatile("cp.async.cg.shared.global [%0], [%1], 16;"
                 :: "r"(dst), "l"(src) : "memory");
}

#define LDSM_X4(r0, r1, r2, r3, a) \
    asm volatile("ldmatrix.sync.aligned.m8n8.x4.shared.b16 {%0,%1,%2,%3}, [%4];" \
                 : "=r"(r0), "=r"(r1), "=r"(r2), "=r"(r3) : "r"(a))

#define MMA16816(d, a, b) \
    asm volatile("mma.sync.aligned.m16n8k16.row.col.f32.bf16.bf16.f32 " \
                 "{%0,%1,%2,%3}, {%4,%5,%6,%7}, {%8,%9}, {%0,%1,%2,%3};" \
                 : "+f"((d)[0]), "+f"((d)[1]), "+f"((d)[2]), "+f"((d)[3]) \
                 : "r"((a)[0]), "r"((a)[1]), "r"((a)[2]), "r"((a)[3]), \
                   "r"((b)[0]), "r"((b)[1]))

// ---------------------------------------------------------------------------
// convert + transpose: src f32 [2][192][65536] -> dhi/dlo bf16 [2][65536][192]
// ---------------------------------------------------------------------------
__global__ __launch_bounds__(256) void convtrans(
    const float* __restrict__ src,
    unsigned short* __restrict__ dhi,
    unsigned short* __restrict__ dlo)
{
    __shared__ float sm[32][33];
    const int p0 = blockIdx.x * 32, c0 = blockIdx.y * 32, b = blockIdx.z;
    const float* s = src + (size_t)b * GK * NPIX;
    const int tc = threadIdx.x & 31, tr = threadIdx.x >> 5;

    #pragma unroll
    for (int i = 0; i < 4; i++) {
        int cl = tr + i * 8;
        sm[cl][tc] = s[(size_t)(c0 + cl) * NPIX + p0 + tc];
    }
    __syncthreads();

    const size_t obase = (size_t)b * NPIX * GK;
    #pragma unroll
    for (int i = 0; i < 4; i++) {
        int pl = tr + i * 8;
        float v = sm[tc][pl];
        __nv_bfloat16 h = __float2bfloat16(v);
        __nv_bfloat16 l = __float2bfloat16(v - __bfloat162float(h));
        size_t o = obase + (size_t)(p0 + pl) * GK + c0 + tc;
        dhi[o] = *(unsigned short*)&h;
        dlo[o] = *(unsigned short*)&l;
    }
}

__global__ void wconvert(const float* __restrict__ w, int n,
                         unsigned short* __restrict__ hi,
                         unsigned short* __restrict__ lo)
{
    int i = blockIdx.x * 256 + threadIdx.x;
    if (i < n) {
        float v = w[i];
        __nv_bfloat16 h = __float2bfloat16(v);
        __nv_bfloat16 l = __float2bfloat16(v - __bfloat162float(h));
        hi[i] = *(unsigned short*)&h;
        lo[i] = *(unsigned short*)&l;
    }
}

// ---------------------------------------------------------------------------
// qkv GEMM, pixel-major output. Single barrier per K-chunk:
//   wait_group 0; sync; issue(c+1); compute(c)
// ---------------------------------------------------------------------------
__global__ __launch_bounds__(256) void gemm_nt(
    const unsigned short* __restrict__ Ahi,
    const unsigned short* __restrict__ Alo,
    const unsigned short* __restrict__ Whi,
    const unsigned short* __restrict__ Wlo,
    float* __restrict__ Cm, int Ntot)
{
    extern __shared__ __align__(16) unsigned short smem[];
    const int t = threadIdx.x, lane = t & 31, w = t >> 5;
    const int bN = blockIdx.x * 64;
    const size_t bM = (size_t)blockIdx.y * 128;
    const int batch = blockIdx.z;
    const int wm0 = (w & 3) * 32;
    const int wn0 = (w >> 2) * 32;

    const uint32_t sb = smem_u32(smem);
    const size_t aoff = ((size_t)batch * NPIX + bM) * GK;
    const unsigned short* gA[2] = { Ahi + aoff, Alo + aoff };
    const unsigned short* gW[2] = { Whi + (size_t)bN * GK, Wlo + (size_t)bN * GK };

    auto issue_chunk = [&](int c) {
        const uint32_t sbase = sb + (uint32_t)(c & 1) * 30720u;
        #pragma unroll
        for (int i = 0; i < 4; i++) {
            int id = t + i * 256;
            int hl = id >> 9, rem = id & 511;
            int row = rem >> 2, c8 = rem & 3;
            uint32_t d = sbase + (uint32_t)(hl * 5120 + row * 40 + c8 * 8) * 2u;
            cp_async16(d, gA[hl] + row * GK + c * 32 + c8 * 8);
        }
        #pragma unroll
        for (int i = 0; i < 2; i++) {
            int id = t + i * 256;
            int hl = id >> 8, rem = id & 255;
            int row = rem >> 2, c8 = rem & 3;
            uint32_t d = sbase + (uint32_t)(10240 + hl * 2560 + row * 40 + c8 * 8) * 2u;
            cp_async16(d, gW[hl] + row * GK + c * 32 + c8 * 8);
        }
        asm volatile("cp.async.commit_group;" ::: "memory");
    };

    float acc[2][4][4];
    #pragma unroll
    for (int mi = 0; mi < 2; mi++)
        #pragma unroll
        for (int ni = 0; ni < 4; ni++)
            #pragma unroll
            for (int r = 0; r < 4; r++) acc[mi][ni][r] = 0.f;

    const int arow  = lane & 15;
    const int akoff = (lane >> 4) * 8;
    const int bg    = lane >> 3;
    const int brow8 = lane & 7;

    issue_chunk(0);
    #pragma unroll 1
    for (int c = 0; c < 6; c++) {
        asm volatile("cp.async.wait_group 0;" ::: "memory");
        __syncthreads();
        if (c + 1 < 6) issue_chunk(c + 1);

        const uint32_t sbase = sb + (uint32_t)(c & 1) * 30720u;
        #pragma unroll
        for (int ks = 0; ks < 2; ks++) {
            const int k0 = ks * 16;
            uint32_t ah[2][4], al[2][4], bh[4][2], bl[4][2];
            #pragma unroll
            for (int mi = 0; mi < 2; mi++) {
                uint32_t off = (uint32_t)((wm0 + mi * 16 + arow) * 40 + k0 + akoff) * 2u;
                LDSM_X4(ah[mi][0], ah[mi][1], ah[mi][2], ah[mi][3], sbase + off);
                LDSM_X4(al[mi][0], al[mi][1], al[mi][2], al[mi][3],
                        sbase + 5120u * 2u + off);
            }
            #pragma unroll
            for (int np = 0; np < 2; np++) {
                uint32_t off = (uint32_t)(10240
                    + (wn0 + (2 * np + (bg >> 1)) * 8 + brow8) * 40
                    + k0 + (bg & 1) * 8) * 2u;
                LDSM_X4(bh[2*np][0], bh[2*np][1], bh[2*np+1][0], bh[2*np+1][1],
                        sbase + off);
                LDSM_X4(bl[2*np][0], bl[2*np][1], bl[2*np+1][0], bl[2*np+1][1],
                        sbase + 2560u * 2u + off);
            }
            #pragma unroll
            for (int mi = 0; mi < 2; mi++)
                #pragma unroll
                for (int ni = 0; ni < 4; ni++)
                    MMA16816(acc[mi][ni], ah[mi], bh[ni]);
            #pragma unroll
            for (int mi = 0; mi < 2; mi++)
                #pragma unroll
                for (int ni = 0; ni < 4; ni++)
                    MMA16816(acc[mi][ni], ah[mi], bl[ni]);
            #pragma unroll
            for (int mi = 0; mi < 2; mi++)
                #pragma unroll
                for (int ni = 0; ni < 4; ni++)
                    MMA16816(acc[mi][ni], al[mi], bh[ni]);
        }
    }

    float* C = Cm + (size_t)batch * NPIX * (size_t)Ntot;
    const int mr = lane >> 2, nc = (lane & 3) * 2;
    #pragma unroll
    for (int mi = 0; mi < 2; mi++)
        #pragma unroll
        for (int ni = 0; ni < 4; ni++) {
            const size_t m = bM + wm0 + mi * 16 + mr;
            const size_t n = (size_t)(bN + wn0 + ni * 8 + nc);
            float* a = acc[mi][ni];
            *(float2*)&C[m * Ntot + n]       = make_float2(a[0], a[1]);
            *(float2*)&C[(m + 8) * Ntot + n] = make_float2(a[2], a[3]);
        }
}

// ---------------------------------------------------------------------------
// proj GEMM, same single-barrier loop.
// ---------------------------------------------------------------------------
__global__ __launch_bounds__(256) void gemm_mma(
    const unsigned short* __restrict__ Ahi,
    const unsigned short* __restrict__ Alo,
    const unsigned short* __restrict__ Bhi,
    const unsigned short* __restrict__ Blo,
    float* __restrict__ Cm, int Mtot)
{
    extern __shared__ __align__(16) unsigned short smem[];
    const int t = threadIdx.x, lane = t & 31, w = t >> 5;
    const int bM = blockIdx.x * 64;
    const size_t bN = (size_t)blockIdx.y * 128;
    const int batch = blockIdx.z;
    const int wm0 = (w >> 2) * 32;
    const int wn0 = (w & 3) * 32;

    const uint32_t sb = smem_u32(smem);
    const unsigned short* gA[2] = { Ahi + (size_t)bM * GK, Alo + (size_t)bM * GK };
    const size_t boff = ((size_t)batch * NPIX + bN) * GK;
    const unsigned short* gB[2] = { Bhi + boff, Blo + boff };

    auto issue_chunk = [&](int c) {
        const uint32_t sbase = sb + (uint32_t)(c & 1) * 30720u;
        #pragma unroll
        for (int i = 0; i < 2; i++) {
            int id = t + i * 256;
            int hl = id >> 8, rem = id & 255;
            int row = rem >> 2, c8 = rem & 3;
            uint32_t d = sbase + (uint32_t)(hl * 2560 + row * 40 + c8 * 8) * 2u;
            cp_async16(d, gA[hl] + row * GK + c * 32 + c8 * 8);
        }
        #pragma unroll
        for (int i = 0; i < 4; i++) {
            int id = t + i * 256;
            int hl = id >> 9, rem = id & 511;
            int row = rem >> 2, c8 = rem & 3;
            uint32_t d = sbase + (uint32_t)(5120 + hl * 5120 + row * 40 + c8 * 8) * 2u;
            cp_async16(d, gB[hl] + row * GK + c * 32 + c8 * 8);
        }
        asm volatile("cp.async.commit_group;" ::: "memory");
    };

    float acc[2][4][4];
    #pragma unroll
    for (int mi = 0; mi < 2; mi++)
        #pragma unroll
        for (int ni = 0; ni < 4; ni++)
            #pragma unroll
            for (int r = 0; r < 4; r++) acc[mi][ni][r] = 0.f;

    const int arow  = lane & 15;
    const int akoff = (lane >> 4) * 8;
    const int bg    = lane >> 3;
    const int brow8 = lane & 7;

    issue_chunk(0);
    #pragma unroll 1
    for (int c = 0; c < 6; c++) {
        asm volatile("cp.async.wait_group 0;" ::: "memory");
        __syncthreads();
        if (c + 1 < 6) issue_chunk(c + 1);

        const uint32_t sbase = sb + (uint32_t)(c & 1) * 30720u;
        #pragma unroll
        for (int ks = 0; ks < 2; ks++) {
            const int k0 = ks * 16;
            uint32_t ah[2][4], al[2][4], bh[4][2], bl[4][2];
            #pragma unroll
            for (int mi = 0; mi < 2; mi++) {
                uint32_t off = (uint32_t)((wm0 + mi * 16 + arow) * 40 + k0 + akoff) * 2u;
                LDSM_X4(ah[mi][0], ah[mi][1], ah[mi][2], ah[mi][3], sbase + off);
                LDSM_X4(al[mi][0], al[mi][1], al[mi][2], al[mi][3],
                        sbase + 2560u * 2u + off);
            }
            #pragma unroll
            for (int np = 0; np < 2; np++) {
                uint32_t off = (uint32_t)(5120
                    + (wn0 + (2 * np + (bg >> 1)) * 8 + brow8) * 40
                    + k0 + (bg & 1) * 8) * 2u;
                LDSM_X4(bh[2*np][0], bh[2*np][1], bh[2*np+1][0], bh[2*np+1][1],
                        sbase + off);
                LDSM_X4(bl[2*np][0], bl[2*np][1], bl[2*np+1][0], bl[2*np+1][1],
                        sbase + 5120u * 2u + off);
            }
            #pragma unroll
            for (int mi = 0; mi < 2; mi++)
                #pragma unroll
                for (int ni = 0; ni < 4; ni++)
                    MMA16816(acc[mi][ni], ah[mi], bh[ni]);
            #pragma unroll
            for (int mi = 0; mi < 2; mi++)
                #pragma unroll
                for (int ni = 0; ni < 4; ni++)
                    MMA16816(acc[mi][ni], ah[mi], bl[ni]);
            #pragma unroll
            for (int mi = 0; mi < 2; mi++)
                #pragma unroll
                for (int ni = 0; ni < 4; ni++)
                    MMA16816(acc[mi][ni], al[mi], bh[ni]);
        }
    }

    float* C = Cm + (size_t)batch * (size_t)Mtot * NPIX;
    const int mr = lane >> 2, nc = (lane & 3) * 2;
    #pragma unroll
    for (int mi = 0; mi < 2; mi++)
        #pragma unroll
        for (int ni = 0; ni < 4; ni++) {
            const size_t m = (size_t)(bM + wm0 + mi * 16 + mr);
            const size_t n = bN + wn0 + ni * 8 + nc;
            float* a = acc[mi][ni];
            *(float2*)&C[m * NPIX + n]       = make_float2(a[0], a[1]);
            *(float2*)&C[(m + 8) * NPIX + n] = make_float2(a[2], a[3]);
        }
}

// ---------------------------------------------------------------------------
// Fused depthwise-3x3 + window channel attention, float4 datapaths.
// Norms: 2 threads/channel (shfl combine). Softmax: 2 threads/row.
// ---------------------------------------------------------------------------
#define ATTN_SMEM_FLOATS (3072 + 3328 + 3072 + 2800 + 216 + 48 + 48)
__global__ __launch_bounds__(256) void window_attn(
    const float* __restrict__ dww,    // [576*9]
    const float* __restrict__ tempr)  // [4]
{
    extern __shared__ __align__(16) float dsm[];
    float* sq      = dsm;              // [48 ch][64 px]
    float* skT     = dsm + 3072;       // [64 px][52 ch]
    float* sv      = dsm + 6400;       // [48 ch][64 px]
    float* scratch = dsm + 9472;       // halo [100][28] -> sattn [48][52]
    float* w4s     = dsm + 12272;      // [9][24]
    float* qin     = dsm + 12488;
    float* kin     = dsm + 12536;

    const int t    = threadIdx.x;
    const int head = blockIdx.x & 3;
    const int win  = blockIdx.x >> 2;
    const int b    = win >> 10;
    const int hn   = (win >> 5) & 31;
    const int wn   = win & 31;
    const int y0   = hn << 3, x0 = wn << 3;

    const size_t pixbase = (size_t)b * NPIX;

    float4 hreg4[3];
    auto load_halo = [&](int chbase) {
        #pragma unroll
        for (int i = 0; i < 3; i++) {
            int e = t + i * 256;
            float4 v = make_float4(0.f, 0.f, 0.f, 0.f);
            if (e < 600) {
                int px = e / 6, c4 = e - px * 6;
                int iy = px / 10, ix = px - iy * 10;
                int gy = y0 - 1 + iy, gx = x0 - 1 + ix;
                if ((unsigned)gy < 256u && (unsigned)gx < 256u)
                    v = *(const float4*)&g_qkv[
                        (pixbase + (size_t)gy * 256 + gx) * 576 + chbase + c4 * 4];
            }
            hreg4[i] = v;
        }
    };
    auto chbase_of = [&](int p) {
        return (p >> 1) * 192 + head * 48 + (p & 1) * 24;
    };

    load_halo(chbase_of(0));
    #pragma unroll 1
    for (int p = 0; p < 6; p++) {
        const int tensor = p >> 1;
        const int half   = p & 1;
        const int gch0   = tensor * 192 + head * 48 + half * 24;

        if (t < 216) {
            int k = t / 24, c = t - k * 24;
            w4s[k * 24 + c] = dww[(gch0 + c) * 9 + k];
        }
        #pragma unroll
        for (int i = 0; i < 3; i++) {
            int e = t + i * 256;
            if (e < 600) {
                int px = e / 6, c4 = e - px * 6;
                *(float4*)&scratch[px * 28 + c4 * 4] = hreg4[i];
            }
        }
        __syncthreads();

        if (p < 5) load_halo(chbase_of(p + 1));

        #pragma unroll
        for (int g = 0; g < 2; g++) {
            int task = t + g * 256;
            if (task < 384) {
                int px = task & 63, c4g = task >> 6;
                int p1 = px >> 3, p2 = px & 7;
                const float* hb = scratch + (p1 * 10 + p2) * 28 + c4g * 4;
                float4 acc = make_float4(0.f, 0.f, 0.f, 0.f);
                #pragma unroll
                for (int k = 0; k < 9; k++) {
                    const int dy = k / 3, dx = k - (k / 3) * 3;
                    float4 h = *(const float4*)&hb[(dy * 10 + dx) * 28];
                    float4 wv = *(const float4*)&w4s[k * 24 + c4g * 4];
                    acc.x = fmaf(h.x, wv.x, acc.x);
                    acc.y = fmaf(h.y, wv.y, acc.y);
                    acc.z = fmaf(h.z, wv.z, acc.z);
                    acc.w = fmaf(h.w, wv.w, acc.w);
                }
                int ch = half * 24 + c4g * 4;
                if (tensor == 0) {
                    sq[(ch + 0) * 64 + px] = acc.x;
                    sq[(ch + 1) * 64 + px] = acc.y;
                    sq[(ch + 2) * 64 + px] = acc.z;
                    sq[(ch + 3) * 64 + px] = acc.w;
                } else if (tensor == 1) {
                    *(float4*)&skT[px * 52 + ch] = acc;
                } else {
                    sv[(ch + 0) * 64 + px] = acc.x;
                    sv[(ch + 1) * 64 + px] = acc.y;
                    sv[(ch + 2) * 64 + px] = acc.z;
                    sv[(ch + 3) * 64 + px] = acc.w;
                }
            }
        }
        __syncthreads();
    }

    // ---- l2 norms: 2 threads per channel, shfl combine ----
    if (t < 96) {
        const int c = t >> 1, half = t & 1;
        float s = 0.f;
        #pragma unroll 8
        for (int i = 0; i < 32; i++) {
            int idx = (i + (t >> 1) + half * 16) & 31;
            float x = sq[c * 64 + half * 32 + idx];
            s = fmaf(x, x, s);
        }
        s += __shfl_xor_sync(0xffffffff, s, 1);
        if (half == 0) qin[c] = 1.f / fmaxf(sqrtf(s), 1e-12f);
    } else if (t >= 128 && t < 224) {
        const int j = (t - 128) >> 1, half = t & 1;
        float s = 0.f;
        #pragma unroll 8
        for (int i = 0; i < 32; i++) {
            int d = half * 32 + ((i + half * 4) & 31);
            float x = skT[d * 52 + j];
            s = fmaf(x, x, s);
        }
        s += __shfl_xor_sync(0xffffffff, s, 1);
        if (half == 0) kin[j] = 1.f / fmaxf(sqrtf(s), 1e-12f);
    }
    __syncthreads();

    float* sattn = scratch;                        // [48][52]
    const float tscale = __ldg(&tempr[head]);

    // ---- logits: 192 threads, 3i x 4j tile ----
    if (t < 192) {
        const int ti = t / 12, tj = t - ti * 12;
        const int i0 = ti * 3, j0 = tj * 4;
        float acc[3][4];
        #pragma unroll
        for (int r = 0; r < 3; r++)
            #pragma unroll
            for (int s = 0; s < 4; s++) acc[r][s] = 0.f;

        for (int d0 = 0; d0 < 64; d0 += 4) {
            float4 qv[3];
            #pragma unroll
            for (int r = 0; r < 3; r++)
                qv[r] = *(const float4*)&sq[(i0 + r) * 64 + d0];
            #pragma unroll
            for (int dd = 0; dd < 4; dd++) {
                float4 kv = *(const float4*)&skT[(d0 + dd) * 52 + j0];
                #pragma unroll
                for (int r = 0; r < 3; r++) {
                    float qd = (dd == 0) ? qv[r].x : (dd == 1) ? qv[r].y
                             : (dd == 2) ? qv[r].z : qv[r].w;
                    acc[r][0] = fmaf(qd, kv.x, acc[r][0]);
                    acc[r][1] = fmaf(qd, kv.y, acc[r][1]);
                    acc[r][2] = fmaf(qd, kv.z, acc[r][2]);
                    acc[r][3] = fmaf(qd, kv.w, acc[r][3]);
                }
            }
        }
        float k0s = kin[j0], k1s = kin[j0 + 1], k2s = kin[j0 + 2], k3s = kin[j0 + 3];
        #pragma unroll
        for (int r = 0; r < 3; r++) {
            float qi = qin[i0 + r] * tscale;
            *(float4*)&sattn[(i0 + r) * 52 + j0] = make_float4(
                acc[r][0] * qi * k0s, acc[r][1] * qi * k1s,
                acc[r][2] * qi * k2s, acc[r][3] * qi * k3s);
        }
    }
    __syncthreads();

    // ---- softmax: 2 threads per row (24 logits each), shfl combine ----
    if (t < 96) {
        const int r = t >> 1, half = t & 1;
        float4 row[6];
        float m = -1e30f;
        #pragma unroll
        for (int g = 0; g < 6; g++) {
            row[g] = *(const float4*)&sattn[r * 52 + half * 24 + g * 4];
            m = fmaxf(m, fmaxf(fmaxf(row[g].x, row[g].y),
                               fmaxf(row[g].z, row[g].w)));
        }
        m = fmaxf(m, __shfl_xor_sync(0xffffffff, m, 1));
        float s = 0.f;
        #pragma unroll
        for (int g = 0; g < 6; g++) {
            row[g].x = __expf(row[g].x - m);
            row[g].y = __expf(row[g].y - m);
            row[g].z = __expf(row[g].z - m);
            row[g].w = __expf(row[g].w - m);
            s += row[g].x + row[g].y + row[g].z + row[g].w;
        }
        s += __shfl_xor_sync(0xffffffff, s, 1);
        float inv = 1.f / s;
        #pragma unroll
        for (int g = 0; g < 6; g++) {
            row[g].x *= inv; row[g].y *= inv;
            row[g].z *= inv; row[g].w *= inv;
            *(float4*)&sattn[r * 52 + half * 24 + g * 4] = row[g];
        }
    }
    __syncthreads();

    // ---- out = attn @ v ; 3i x 4d tile ----
    uint32_t* stg = (uint32_t*)skT;                // [64 px][52 ch]
    {
        const int td = t & 15;
        const int ti = t >> 4;
        const int d0 = td * 4, i0 = ti * 3;
        float acc[3][4];
        #pragma unroll
        for (int r = 0; r < 3; r++)
            #pragma unroll
            for (int s = 0; s < 4; s++) acc[r][s] = 0.f;

        #pragma unroll 2
        for (int jg = 0; jg < 12; jg++) {
            const int j = jg * 4;
            float4 a0 = *(const float4*)&sattn[(i0 + 0) * 52 + j];
            float4 a1 = *(const float4*)&sattn[(i0 + 1) * 52 + j];
            float4 a2 = *(const float4*)&sattn[(i0 + 2) * 52 + j];
            float4 v0 = *(const float4*)&sv[(j + 0) * 64 + d0];
            float4 v1 = *(const float4*)&sv[(j + 1) * 64 + d0];
            float4 v2 = *(const float4*)&sv[(j + 2) * 64 + d0];
            float4 v3 = *(const float4*)&sv[(j + 3) * 64 + d0];
            #pragma unroll
            for (int r = 0; r < 3; r++) {
                float4 a = (r == 0) ? a0 : (r == 1) ? a1 : a2;
                acc[r][0] = fmaf(a.x, v0.x, acc[r][0]);
                acc[r][1] = fmaf(a.x, v0.y, acc[r][1]);
                acc[r][2] = fmaf(a.x, v0.z, acc[r][2]);
                acc[r][3] = fmaf(a.x, v0.w, acc[r][3]);
                acc[r][0] = fmaf(a.y, v1.x, acc[r][0]);
                acc[r][1] = fmaf(a.y, v1.y, acc[r][1]);
                acc[r][2] = fmaf(a.y, v1.z, acc[r][2]);
                acc[r][3] = fmaf(a.y, v1.w, acc[r][3]);
                acc[r][0] = fmaf(a.z, v2.x, acc[r][0]);
                acc[r][1] = fmaf(a.z, v2.y, acc[r][1]);
                acc[r][2] = fmaf(a.z, v2.z, acc[r][2]);
                acc[r][3] = fmaf(a.z, v2.w, acc[r][3]);
                acc[r][0] = fmaf(a.w, v3.x, acc[r][0]);
                acc[r][1] = fmaf(a.w, v3.y, acc[r][1]);
                acc[r][2] = fmaf(a.w, v3.z, acc[r][2]);
                acc[r][3] = fmaf(a.w, v3.w, acc[r][3]);
            }
        }
        __syncthreads();                           // skT readers done
        #pragma unroll
        for (int r = 0; r < 3; r++)
            #pragma unroll
            for (int s = 0; s < 4; s++) {
                float v = acc[r][s];
                __nv_bfloat16 h = __float2bfloat16(v);
                __nv_bfloat16 l = __float2bfloat16(v - __bfloat162float(h));
                stg[(d0 + s) * 52 + i0 + r] =
                    (uint32_t)*(unsigned short*)&h
                    | ((uint32_t)*(unsigned short*)&l << 16);
            }
    }
    __syncthreads();

    // cooperative transposed writeout -> g_bth/g_btl [b][pix][192]
    #pragma unroll
    for (int i = 0; i < 6; i++) {
        int id = t + i * 256;
        int row = id / 24, cp = id - row * 24;
        int c = cp * 2;
        uint32_t w0 = stg[row * 52 + c];
        uint32_t w1 = stg[row * 52 + c + 1];
        int p1 = row >> 3, p2 = row & 7;
        size_t o = (pixbase + (size_t)(y0 + p1) * 256 + (x0 + p2)) * GK
                 + head * 48 + c;
        *(ushort2*)&g_bth[o] = make_ushort2((unsigned short)w0, (unsigned short)w1);
        *(ushort2*)&g_btl[o] = make_ushort2((unsigned short)(w0 >> 16),
                                            (unsigned short)(w1 >> 16));
    }
}

// ---------------------------------------------------------------------------
extern "C" void kernel_launch(void* const* d_in, const int* in_sizes, int n_in,
                              void* d_out, int out_size)
{
    const float *x = nullptr, *qw = nullptr, *dw = nullptr, *pw = nullptr, *tp = nullptr;
    for (int i = 0; i < n_in; i++) {
        switch (in_sizes[i]) {
            case 25165824: x  = (const float*)d_in[i]; break;  // x [2,192,256,256]
            case 110592:   qw = (const float*)d_in[i]; break;  // qkv_w [576,192]
            case 5184:     dw = (const float*)d_in[i]; break;  // dw_w [576,1,3,3]
            case 36864:    pw = (const float*)d_in[i]; break;  // proj_w [192,192]
            case 4:        tp = (const float*)d_in[i]; break;  // temperature [4]
        }
    }

    void *qkvp, *bthp, *btlp, *wqhp, *wqlp, *wphp, *wplp;
    cudaGetSymbolAddress(&qkvp, g_qkv);
    cudaGetSymbolAddress(&bthp, g_bth);
    cudaGetSymbolAddress(&btlp, g_btl);
    cudaGetSymbolAddress(&wqhp, g_wqh);
    cudaGetSymbolAddress(&wqlp, g_wql);
    cudaGetSymbolAddress(&wphp, g_wph);
    cudaGetSymbolAddress(&wplp, g_wpl);

    const int GEMM_SMEM = 2 * 30720;               // 61440 B -> 3 CTAs/SM
    const int ATTN_SMEM = ATTN_SMEM_FLOATS * 4;    // 50336 B -> 4 CTAs/SM
    cudaFuncSetAttribute(gemm_nt,  cudaFuncAttributeMaxDynamicSharedMemorySize, GEMM_SMEM);
    cudaFuncSetAttribute(gemm_mma, cudaFuncAttributeMaxDynamicSharedMemorySize, GEMM_SMEM);
    cudaFuncSetAttribute(window_attn, cudaFuncAttributeMaxDynamicSharedMemorySize, ATTN_SMEM);

    wconvert<<<(110592 + 255) / 256, 256>>>(qw, 110592,
        (unsigned short*)wqhp, (unsigned short*)wqlp);
    wconvert<<<(36864 + 255) / 256, 256>>>(pw, 36864,
        (unsigned short*)wphp, (unsigned short*)wplp);

    // 1) x -> x^T bf16 hi/lo  ([b][pix][192])
    convtrans<<<dim3(2048, 6, 2), 256>>>(x,
        (unsigned short*)bthp, (unsigned short*)btlp);

    // 2) qkv GEMM, pixel-major output: g_qkv[b][pix][576]
    gemm_nt<<<dim3(9, 512, 2), 256, GEMM_SMEM>>>(
        (const unsigned short*)bthp, (const unsigned short*)btlp,
        (const unsigned short*)wqhp, (const unsigned short*)wqlp,
        (float*)qkvp, 576);

    // 3) fused depthwise 3x3 + attention; writes bf16 hi/lo transposed
    window_attn<<<8192, 256, ATTN_SMEM>>>(dw, tp);

    // 4) proj GEMM -> d_out ([b][192][65536], ch-major)
    gemm_mma<<<dim3(3, 512, 2), 256, GEMM_SMEM>>>(
        (const unsigned short*)wphp, (const unsigned short*)wplp,
        (const unsigned short*)bthp, (const unsigned short*)btlp,
        (float*)d_out, 192);
}